// round 11
// baseline (speedup 1.0000x reference)
#include <cuda_runtime.h>
#include <cuda_bf16.h>
#include <cuda_fp16.h>
#include <cstdint>

// Fused GraphSAGE layer, three kernels in one graph:
//  K1 : feature table fp32 -> fp16 into __device__ scratch (102MB, L2-warm)
//  K1b: W fp32 -> tf32 into __device__ scratch (256KB)
//  K2 : fp16 gather (R9 structure) + mean, tf32 mma.sync GEMM with
//       pre-converted W staged via smem (raw copy), bias/relu,
//       shuffle row L2-norm, streaming store.

#define BM      32
#define DDIM    256
#define THREADS 512
#define MAX_S   40
#define ASTRIDE 260     // A tile row stride (words)
#define WSTRIDE 264     // W chunk row stride (words)
#define NTAB_CAP 200000 // fp16 table capacity (rows)

#define AS_BYTES  (BM * ASTRIDE * 4)
#define WS_BYTES  (2 * 8 * WSTRIDE * 4)
#define IDX_BYTES (BM * MAX_S * 4)
#define R2_BYTES  (WS_BYTES > IDX_BYTES ? WS_BYTES : IDX_BYTES)
#define SMEM_BYTES (AS_BYTES + R2_BYTES + 128)

// fp16 feature table: 200000 x 256 x 2B = 102.4 MB (32 uint4 per row)
__device__ uint4 g_feat16[(size_t)NTAB_CAP * 32];
// tf32 W: 256 x 256 x 4B = 256 KB (16384 uint4)
__device__ uint4 g_wtf32[DDIM * DDIM / 4];

__device__ __forceinline__ uint32_t f2tf32(float f) {
    uint32_t u;
    asm("cvt.rna.tf32.f32 %0, %1;" : "=r"(u) : "f"(f));
    return u;
}

__device__ __forceinline__ int ldg_stream(const int* p) {
    int v;
    asm("ld.global.cs.s32 %0, [%1];" : "=r"(v) : "l"(p));
    return v;
}

__device__ __forceinline__ float4 ldg_stream4(const float4* p) {
    float4 v;
    asm("ld.global.cs.v4.f32 {%0,%1,%2,%3}, [%4];"
        : "=f"(v.x), "=f"(v.y), "=f"(v.z), "=f"(v.w) : "l"(p));
    return v;
}

__device__ __forceinline__ void stg_stream(float4* p, float4 v) {
    asm volatile("st.global.cs.v4.f32 [%0], {%1,%2,%3,%4};"
                 :: "l"(p), "f"(v.x), "f"(v.y), "f"(v.z), "f"(v.w));
}

__device__ __forceinline__ void mma_tf32(float* d,
                                         uint32_t a0, uint32_t a1,
                                         uint32_t a2, uint32_t a3,
                                         uint32_t b0, uint32_t b1)
{
    asm("mma.sync.aligned.m16n8k8.row.col.f32.tf32.tf32.f32 "
        "{%0,%1,%2,%3}, {%4,%5,%6,%7}, {%8,%9}, {%0,%1,%2,%3};"
        : "+f"(d[0]), "+f"(d[1]), "+f"(d[2]), "+f"(d[3])
        : "r"(a0), "r"(a1), "r"(a2), "r"(a3), "r"(b0), "r"(b1));
}

// ---- K1: fp32 -> fp16 table conversion ----
__global__ void cvt_f16_kernel(const float4* __restrict__ F4, int n_vec)
{
    int i      = blockIdx.x * blockDim.x + threadIdx.x;
    int stride = gridDim.x * blockDim.x;
    for (; i < n_vec; i += stride) {
        float4 f0 = ldg_stream4(F4 + 2 * (long)i);
        float4 f1 = ldg_stream4(F4 + 2 * (long)i + 1);
        __half2 h0 = __float22half2_rn(make_float2(f0.x, f0.y));
        __half2 h1 = __float22half2_rn(make_float2(f0.z, f0.w));
        __half2 h2 = __float22half2_rn(make_float2(f1.x, f1.y));
        __half2 h3 = __float22half2_rn(make_float2(f1.z, f1.w));
        uint4 u;
        u.x = *reinterpret_cast<uint32_t*>(&h0);
        u.y = *reinterpret_cast<uint32_t*>(&h1);
        u.z = *reinterpret_cast<uint32_t*>(&h2);
        u.w = *reinterpret_cast<uint32_t*>(&h3);
        g_feat16[i] = u;
    }
}

// ---- K1b: W fp32 -> tf32 ----
__global__ void cvt_w_kernel(const float4* __restrict__ W4)
{
    int i = blockIdx.x * blockDim.x + threadIdx.x;   // 16384 uint4
    float4 w = W4[i];
    uint4 u = { f2tf32(w.x), f2tf32(w.y), f2tf32(w.z), f2tf32(w.w) };
    g_wtf32[i] = u;
}

// ---- K2: gather + GEMM + epilogue ----
template<bool USE_F16>
__global__ __launch_bounds__(THREADS, 2)
void gsage_tc_kernel(const int*   __restrict__ node_idx,
                     const int*   __restrict__ neigh_idx,
                     const float* __restrict__ features,
                     const float* __restrict__ W,
                     const float* __restrict__ b,
                     float*       __restrict__ out,
                     int n_nodes, int n_samp)
{
    extern __shared__ char smem[];
    float*    As   = reinterpret_cast<float*>(smem);               // [32][260]
    int*      idxS = reinterpret_cast<int*>(smem + AS_BYTES);      // gather only
    uint32_t* Ws   = reinterpret_cast<uint32_t*>(smem + AS_BYTES); // gemm only
    float*    invN = reinterpret_cast<float*>(smem + AS_BYTES + R2_BYTES);

    const int tid       = threadIdx.x;
    const int blockBase = blockIdx.x * BM;
    const int rows      = min(BM, n_nodes - blockBase);
    const int S         = n_samp + 1;

    // ---- stage indices: slot 0 = self, slots 1..n_samp = neighbors ----
    for (int i = tid; i < rows * S; i += THREADS) {
        int n = i / S, s = i - n * S;
        int gn = blockBase + n;
        idxS[n * S + s] = (s == 0) ? ldg_stream(node_idx + gn)
                                   : ldg_stream(neigh_idx + (long)gn * n_samp + (s - 1));
    }
    __syncthreads();

    const float invS = 1.0f / (float)S;

    if (USE_F16) {
        // ---- fp16 gather (R9): warp w -> nodes 2w,2w+1; lane -> 16B frag ----
        const int lane = tid & 31;
        const int w    = tid >> 5;
        const int n0 = 2 * w, n1 = 2 * w + 1;
        const bool v0 = n0 < rows, v1 = n1 < rows;
        const int* ip0 = idxS + (v0 ? n0 * S : 0);
        const int* ip1 = idxS + (v1 ? n1 * S : 0);

        float acc0[8], acc1[8];
        #pragma unroll
        for (int j = 0; j < 8; ++j) { acc0[j] = 0.0f; acc1[j] = 0.0f; }

        #pragma unroll 4
        for (int s = 0; s < S; ++s) {
            uint4 u0 = g_feat16[(long)ip0[s] * 32 + lane];
            uint4 u1 = g_feat16[(long)ip1[s] * 32 + lane];
            const __half2* h0 = reinterpret_cast<const __half2*>(&u0);
            const __half2* h1 = reinterpret_cast<const __half2*>(&u1);
            #pragma unroll
            for (int j = 0; j < 4; ++j) {
                float2 f0 = __half22float2(h0[j]);
                float2 f1 = __half22float2(h1[j]);
                acc0[2*j]   += f0.x; acc0[2*j+1] += f0.y;
                acc1[2*j]   += f1.x; acc1[2*j+1] += f1.y;
            }
        }

        const float m0 = v0 ? invS : 0.0f, m1 = v1 ? invS : 0.0f;
        uint4 o0a, o0b, o1a, o1b;
        o0a.x = f2tf32(acc0[0]*m0); o0a.y = f2tf32(acc0[1]*m0);
        o0a.z = f2tf32(acc0[2]*m0); o0a.w = f2tf32(acc0[3]*m0);
        o0b.x = f2tf32(acc0[4]*m0); o0b.y = f2tf32(acc0[5]*m0);
        o0b.z = f2tf32(acc0[6]*m0); o0b.w = f2tf32(acc0[7]*m0);
        o1a.x = f2tf32(acc1[0]*m1); o1a.y = f2tf32(acc1[1]*m1);
        o1a.z = f2tf32(acc1[2]*m1); o1a.w = f2tf32(acc1[3]*m1);
        o1b.x = f2tf32(acc1[4]*m1); o1b.y = f2tf32(acc1[5]*m1);
        o1b.z = f2tf32(acc1[6]*m1); o1b.w = f2tf32(acc1[7]*m1);
        *reinterpret_cast<uint4*>(&As[n0 * ASTRIDE + 8 * lane])     = o0a;
        *reinterpret_cast<uint4*>(&As[n0 * ASTRIDE + 8 * lane + 4]) = o0b;
        *reinterpret_cast<uint4*>(&As[n1 * ASTRIDE + 8 * lane])     = o1a;
        *reinterpret_cast<uint4*>(&As[n1 * ASTRIDE + 8 * lane + 4]) = o1b;
    } else {
        // ---- fp32 fallback gather ----
        const int c4 = tid & 63;
        const int n0 = (tid >> 6) * 4;
        const float4* F4 = reinterpret_cast<const float4*>(features);

        const bool v0 = (n0 + 0) < rows, v1 = (n0 + 1) < rows;
        const bool v2 = (n0 + 2) < rows, v3 = (n0 + 3) < rows;
        const int* ip0 = idxS + (v0 ? (n0 + 0) * S : 0);
        const int* ip1 = idxS + (v1 ? (n0 + 1) * S : 0);
        const int* ip2 = idxS + (v2 ? (n0 + 2) * S : 0);
        const int* ip3 = idxS + (v3 ? (n0 + 3) * S : 0);

        float4 a0 = {0,0,0,0}, a1 = {0,0,0,0}, a2 = {0,0,0,0}, a3 = {0,0,0,0};
        #pragma unroll 4
        for (int s = 0; s < S; ++s) {
            float4 t0 = __ldg(F4 + (long)ip0[s] * (DDIM/4) + c4);
            float4 t1 = __ldg(F4 + (long)ip1[s] * (DDIM/4) + c4);
            float4 t2 = __ldg(F4 + (long)ip2[s] * (DDIM/4) + c4);
            float4 t3 = __ldg(F4 + (long)ip3[s] * (DDIM/4) + c4);
            a0.x += t0.x; a0.y += t0.y; a0.z += t0.z; a0.w += t0.w;
            a1.x += t1.x; a1.y += t1.y; a1.z += t1.z; a1.w += t1.w;
            a2.x += t2.x; a2.y += t2.y; a2.z += t2.z; a2.w += t2.w;
            a3.x += t3.x; a3.y += t3.y; a3.z += t3.z; a3.w += t3.w;
        }
        const float m0 = v0 ? invS : 0.0f, m1 = v1 ? invS : 0.0f;
        const float m2 = v2 ? invS : 0.0f, m3 = v3 ? invS : 0.0f;
        uint4 u0 = { f2tf32(a0.x*m0), f2tf32(a0.y*m0), f2tf32(a0.z*m0), f2tf32(a0.w*m0) };
        uint4 u1 = { f2tf32(a1.x*m1), f2tf32(a1.y*m1), f2tf32(a1.z*m1), f2tf32(a1.w*m1) };
        uint4 u2 = { f2tf32(a2.x*m2), f2tf32(a2.y*m2), f2tf32(a2.z*m2), f2tf32(a2.w*m2) };
        uint4 u3 = { f2tf32(a3.x*m3), f2tf32(a3.y*m3), f2tf32(a3.z*m3), f2tf32(a3.w*m3) };
        *reinterpret_cast<uint4*>(&As[(n0 + 0) * ASTRIDE + 4 * c4]) = u0;
        *reinterpret_cast<uint4*>(&As[(n0 + 1) * ASTRIDE + 4 * c4]) = u1;
        *reinterpret_cast<uint4*>(&As[(n0 + 2) * ASTRIDE + 4 * c4]) = u2;
        *reinterpret_cast<uint4*>(&As[(n0 + 3) * ASTRIDE + 4 * c4]) = u3;
    }
    __syncthreads();   // As ready; idxS dead -> Ws region live

    // ---- tensor-core GEMM: tf32 m16n8k8, pre-converted W staged via smem ----
    const int lane = tid & 31, warp = tid >> 5;
    const int g    = lane >> 2, t = lane & 3;
    const int mrow  = (warp & 1) * 16;
    const int nbase = (warp >> 1) * 32;

    const int kk = tid >> 6;           // staging row 0..7
    const int c4 = tid & 63;           // staging uint4 col

    float d[4][4];
    #pragma unroll
    for (int j = 0; j < 4; ++j)
        #pragma unroll
        for (int c = 0; c < 4; ++c) d[j][c] = 0.0f;

    const uint32_t* a_lo = reinterpret_cast<const uint32_t*>(As) + (mrow + g) * ASTRIDE;
    const uint32_t* a_hi = a_lo + 8 * ASTRIDE;

    // prologue: stage chunk 0 (raw copy — W already tf32)
    *reinterpret_cast<uint4*>(&Ws[kk * WSTRIDE + 4 * c4]) = g_wtf32[kk * 64 + c4];
    __syncthreads();

    for (int kc = 0; kc < DDIM / 8; ++kc) {
        const uint32_t* Wb = Ws + (kc & 1) * (8 * WSTRIDE);

        if (kc + 1 < DDIM / 8) {
            *reinterpret_cast<uint4*>(
                &Ws[((kc + 1) & 1) * (8 * WSTRIDE) + kk * WSTRIDE + 4 * c4]) =
                g_wtf32[((kc + 1) * 8 + kk) * 64 + c4];
        }

        const int k0 = kc * 8;
        uint32_t fa0 = a_lo[k0 + t];
        uint32_t fa1 = a_hi[k0 + t];
        uint32_t fa2 = a_lo[k0 + t + 4];
        uint32_t fa3 = a_hi[k0 + t + 4];

        #pragma unroll
        for (int j = 0; j < 4; ++j) {
            int n = nbase + 8 * j + g;
            uint32_t b0 = Wb[t * WSTRIDE + n];
            uint32_t b1 = Wb[(t + 4) * WSTRIDE + n];
            mma_tf32(d[j], fa0, fa1, fa2, fa3, b0, b1);
        }
        __syncthreads();
    }

    // ---- epilogue: bias + relu into smem (overwrite As) ----
    #pragma unroll
    for (int j = 0; j < 4; ++j) {
        int col = nbase + 8 * j + 2 * t;
        float2 bb = __ldg(reinterpret_cast<const float2*>(b + col));
        float2 lo, hi;
        lo.x = fmaxf(d[j][0] + bb.x, 0.0f);
        lo.y = fmaxf(d[j][1] + bb.y, 0.0f);
        hi.x = fmaxf(d[j][2] + bb.x, 0.0f);
        hi.y = fmaxf(d[j][3] + bb.y, 0.0f);
        *reinterpret_cast<float2*>(&As[(mrow + g)     * ASTRIDE + col]) = lo;
        *reinterpret_cast<float2*>(&As[(mrow + g + 8) * ASTRIDE + col]) = hi;
    }
    __syncthreads();

    // ---- per-row L2 norm: warp w handles rows 2w, 2w+1 ----
    #pragma unroll
    for (int rr = 0; rr < 2; ++rr) {
        int row = warp * 2 + rr;
        float s = 0.0f;
        #pragma unroll
        for (int jj = 0; jj < 8; ++jj) {
            float v = As[row * ASTRIDE + lane + 32 * jj];
            s = fmaf(v, v, s);
        }
        #pragma unroll
        for (int o = 16; o > 0; o >>= 1)
            s += __shfl_xor_sync(0xffffffffu, s, o);
        if (lane == 0)
            invN[row] = 1.0f / fmaxf(sqrtf(s), 1e-12f);
    }
    __syncthreads();

    // ---- normalized streaming store ----
    float4* out4 = reinterpret_cast<float4*>(out);
    for (int i = tid; i < BM * (DDIM / 4); i += THREADS) {
        int r = i >> 6, c = i & 63;
        if (r < rows) {
            float4 v = *reinterpret_cast<const float4*>(&As[r * ASTRIDE + 4 * c]);
            float sc = invN[r];
            v.x *= sc; v.y *= sc; v.z *= sc; v.w *= sc;
            stg_stream(out4 + (long)(blockBase + r) * (DDIM / 4) + c, v);
        }
    }
}

extern "C" void kernel_launch(void* const* d_in, const int* in_sizes, int n_in,
                              void* d_out, int out_size)
{
    const int*   node_idx  = (const int*)  d_in[0];
    const int*   neigh_idx = (const int*)  d_in[1];
    const float* features  = (const float*)d_in[2];
    const float* W         = (const float*)d_in[3];
    const float* b         = (const float*)d_in[4];
    float*       out       = (float*)      d_out;

    const int n_nodes = in_sizes[0];
    const int n_samp  = in_sizes[1] / n_nodes;   // 32
    const int n_table = in_sizes[2] / DDIM;
    const int grid    = (n_nodes + BM - 1) / BM;

    // W -> tf32 (always; used by both paths)
    cvt_w_kernel<<<DDIM * DDIM / 4 / 512, 512>>>(
        reinterpret_cast<const float4*>(W));

    if (n_table <= NTAB_CAP) {
        const int n_vec = n_table * 32;
        cvt_f16_kernel<<<3125, 512>>>(
            reinterpret_cast<const float4*>(features), n_vec);

        cudaFuncSetAttribute(gsage_tc_kernel<true>,
                             cudaFuncAttributeMaxDynamicSharedMemorySize, SMEM_BYTES);
        gsage_tc_kernel<true><<<grid, THREADS, SMEM_BYTES>>>(
            node_idx, neigh_idx, features, W, b, out, n_nodes, n_samp);
    } else {
        cudaFuncSetAttribute(gsage_tc_kernel<false>,
                             cudaFuncAttributeMaxDynamicSharedMemorySize, SMEM_BYTES);
        gsage_tc_kernel<false><<<grid, THREADS, SMEM_BYTES>>>(
            node_idx, neigh_idx, features, W, b, out, n_nodes, n_samp);
    }
}

// round 12
// speedup vs baseline: 1.1393x; 1.1393x over previous
#include <cuda_runtime.h>
#include <cuda_bf16.h>
#include <cuda_fp16.h>
#include <cstdint>

// Fused GraphSAGE layer, split pipeline (one graph):
//  K1 : feature table fp32 -> fp16 into __device__ scratch (102MB, L2-warm)
//  K2a: gather+mean at high occupancy (48 warps/SM), agg -> tf32 scratch
//  K2b: tf32 mma.sync GEMM (R9-exact, in-loop W cvt), bias/relu,
//       shuffle row L2-norm, streaming store.
// Fallback: fused fp32 kernel when table/node caps exceeded.

#define BM      32
#define DDIM    256
#define THREADS 512
#define MAX_S   40
#define ASTRIDE 260     // A tile row stride (words)
#define WSTRIDE 264     // W chunk row stride (words)
#define NTAB_CAP 200000 // fp16 table capacity (rows)
#define NODE_CAP 65536  // agg scratch capacity (rows)
#define GW      16      // nodes (warps) per gather block

#define AS_BYTES  (BM * ASTRIDE * 4)
#define WS_BYTES  (2 * 8 * WSTRIDE * 4)
#define IDX_BYTES (BM * MAX_S * 4)
#define R2_BYTES  (WS_BYTES > IDX_BYTES ? WS_BYTES : IDX_BYTES)
#define SMEM_BYTES (AS_BYTES + R2_BYTES + 128)

// fp16 feature table: 200000 x 256 x 2B = 102.4 MB (32 uint4 per row)
__device__ uint4 g_feat16[(size_t)NTAB_CAP * 32];
// tf32 agg scratch: 65536 x 256 x 4B = 67 MB (64 uint4 per row)
__device__ uint4 g_agg[(size_t)NODE_CAP * 64];

__device__ __forceinline__ uint32_t f2tf32(float f) {
    uint32_t u;
    asm("cvt.rna.tf32.f32 %0, %1;" : "=r"(u) : "f"(f));
    return u;
}

__device__ __forceinline__ int ldg_stream(const int* p) {
    int v;
    asm("ld.global.cs.s32 %0, [%1];" : "=r"(v) : "l"(p));
    return v;
}

__device__ __forceinline__ float4 ldg_stream4(const float4* p) {
    float4 v;
    asm("ld.global.cs.v4.f32 {%0,%1,%2,%3}, [%4];"
        : "=f"(v.x), "=f"(v.y), "=f"(v.z), "=f"(v.w) : "l"(p));
    return v;
}

__device__ __forceinline__ void stg_stream(float4* p, float4 v) {
    asm volatile("st.global.cs.v4.f32 [%0], {%1,%2,%3,%4};"
                 :: "l"(p), "f"(v.x), "f"(v.y), "f"(v.z), "f"(v.w));
}

__device__ __forceinline__ void mma_tf32(float* d,
                                         uint32_t a0, uint32_t a1,
                                         uint32_t a2, uint32_t a3,
                                         uint32_t b0, uint32_t b1)
{
    asm("mma.sync.aligned.m16n8k8.row.col.f32.tf32.tf32.f32 "
        "{%0,%1,%2,%3}, {%4,%5,%6,%7}, {%8,%9}, {%0,%1,%2,%3};"
        : "+f"(d[0]), "+f"(d[1]), "+f"(d[2]), "+f"(d[3])
        : "r"(a0), "r"(a1), "r"(a2), "r"(a3), "r"(b0), "r"(b1));
}

// accumulate one fp16 row fragment (8 halves) into 8 float accumulators
__device__ __forceinline__ void acc_single(float* acc, uint4 x) {
    const __half2* hx = reinterpret_cast<const __half2*>(&x);
    #pragma unroll
    for (int j = 0; j < 4; ++j) {
        float2 f = __half22float2(hx[j]);
        acc[2*j]   += f.x;
        acc[2*j+1] += f.y;
    }
}

// ---- K1: fp32 -> fp16 table conversion ----
__global__ void cvt_f16_kernel(const float4* __restrict__ F4, int n_vec)
{
    int i      = blockIdx.x * blockDim.x + threadIdx.x;
    int stride = gridDim.x * blockDim.x;
    for (; i < n_vec; i += stride) {
        float4 f0 = ldg_stream4(F4 + 2 * (long)i);
        float4 f1 = ldg_stream4(F4 + 2 * (long)i + 1);
        __half2 h0 = __float22half2_rn(make_float2(f0.x, f0.y));
        __half2 h1 = __float22half2_rn(make_float2(f0.z, f0.w));
        __half2 h2 = __float22half2_rn(make_float2(f1.x, f1.y));
        __half2 h3 = __float22half2_rn(make_float2(f1.z, f1.w));
        uint4 u;
        u.x = *reinterpret_cast<uint32_t*>(&h0);
        u.y = *reinterpret_cast<uint32_t*>(&h1);
        u.z = *reinterpret_cast<uint32_t*>(&h2);
        u.w = *reinterpret_cast<uint32_t*>(&h3);
        g_feat16[i] = u;
    }
}

// ---- K2a: high-occupancy gather+mean -> tf32 agg scratch ----
__global__ __launch_bounds__(THREADS, 3)
void gather_kernel(const int* __restrict__ node_idx,
                   const int* __restrict__ neigh_idx,
                   int n_nodes, int n_samp)
{
    __shared__ int idxS[GW * MAX_S];

    const int tid       = threadIdx.x;
    const int blockBase = blockIdx.x * GW;
    const int rows      = min(GW, n_nodes - blockBase);
    const int S         = n_samp + 1;

    for (int i = tid; i < rows * S; i += THREADS) {
        int n = i / S, s = i - n * S;
        int gn = blockBase + n;
        idxS[n * S + s] = (s == 0) ? ldg_stream(node_idx + gn)
                                   : ldg_stream(neigh_idx + (long)gn * n_samp + (s - 1));
    }
    __syncthreads();

    const int lane = tid & 31;
    const int w    = tid >> 5;          // warp = node within block
    if (w >= rows) return;              // no barriers after this point
    const int* ip = idxS + w * S;

    float acc[8];
    #pragma unroll
    for (int j = 0; j < 8; ++j) acc[j] = 0.0f;

    int s = 0;
    #pragma unroll 1
    for (; s + 4 <= S; s += 4) {        // 4 independent row loads in flight
        uint4 u0 = g_feat16[(long)ip[s + 0] * 32 + lane];
        uint4 u1 = g_feat16[(long)ip[s + 1] * 32 + lane];
        uint4 u2 = g_feat16[(long)ip[s + 2] * 32 + lane];
        uint4 u3 = g_feat16[(long)ip[s + 3] * 32 + lane];
        acc_single(acc, u0);
        acc_single(acc, u1);
        acc_single(acc, u2);
        acc_single(acc, u3);
    }
    for (; s < S; ++s) {
        uint4 u = g_feat16[(long)ip[s] * 32 + lane];
        acc_single(acc, u);
    }

    const float invS = 1.0f / (float)S;
    uint4 oa, ob;
    oa.x = f2tf32(acc[0] * invS); oa.y = f2tf32(acc[1] * invS);
    oa.z = f2tf32(acc[2] * invS); oa.w = f2tf32(acc[3] * invS);
    ob.x = f2tf32(acc[4] * invS); ob.y = f2tf32(acc[5] * invS);
    ob.z = f2tf32(acc[6] * invS); ob.w = f2tf32(acc[7] * invS);

    size_t base = (size_t)(blockBase + w) * 64 + 2 * lane;
    g_agg[base]     = oa;
    g_agg[base + 1] = ob;
}

// ---- K2b: tf32 GEMM + epilogue (A from scratch) ----
__global__ __launch_bounds__(THREADS, 2)
void gemm_kernel(const float* __restrict__ W,
                 const float* __restrict__ b,
                 float*       __restrict__ out,
                 int n_nodes)
{
    extern __shared__ char smem[];
    float*    As   = reinterpret_cast<float*>(smem);               // [32][260]
    uint32_t* Ws   = reinterpret_cast<uint32_t*>(smem + AS_BYTES);
    float*    invN = reinterpret_cast<float*>(smem + AS_BYTES + R2_BYTES);

    const int tid       = threadIdx.x;
    const int blockBase = blockIdx.x * BM;
    const int rows      = min(BM, n_nodes - blockBase);

    // ---- load A tile (already tf32 bits) into padded smem ----
    const uint4* A4 = g_agg + (size_t)blockBase * 64;
    for (int i = tid; i < BM * 64; i += THREADS) {
        int r = i >> 6, c = i & 63;
        *reinterpret_cast<uint4*>(&As[r * ASTRIDE + 4 * c]) = A4[i];
    }
    __syncthreads();

    // ---- tensor-core GEMM: tf32 m16n8k8, W staged via smem (R9-exact) ----
    const int lane = tid & 31, warp = tid >> 5;
    const int g    = lane >> 2, t = lane & 3;
    const int mrow  = (warp & 1) * 16;
    const int nbase = (warp >> 1) * 32;

    const int kk = tid >> 6;
    const int n4 = (tid & 63) * 4;

    float d[4][4];
    #pragma unroll
    for (int j = 0; j < 4; ++j)
        #pragma unroll
        for (int c = 0; c < 4; ++c) d[j][c] = 0.0f;

    const uint32_t* a_lo = reinterpret_cast<const uint32_t*>(As) + (mrow + g) * ASTRIDE;
    const uint32_t* a_hi = a_lo + 8 * ASTRIDE;

    {
        float4 w = *reinterpret_cast<const float4*>(&W[kk * DDIM + n4]);
        uint4 u = { f2tf32(w.x), f2tf32(w.y), f2tf32(w.z), f2tf32(w.w) };
        *reinterpret_cast<uint4*>(&Ws[kk * WSTRIDE + n4]) = u;
    }
    __syncthreads();

    for (int kc = 0; kc < DDIM / 8; ++kc) {
        const uint32_t* Wb = Ws + (kc & 1) * (8 * WSTRIDE);

        if (kc + 1 < DDIM / 8) {
            float4 w = *reinterpret_cast<const float4*>(
                           &W[((kc + 1) * 8 + kk) * DDIM + n4]);
            uint4 u = { f2tf32(w.x), f2tf32(w.y), f2tf32(w.z), f2tf32(w.w) };
            *reinterpret_cast<uint4*>(
                &Ws[((kc + 1) & 1) * (8 * WSTRIDE) + kk * WSTRIDE + n4]) = u;
        }

        const int k0 = kc * 8;
        uint32_t fa0 = a_lo[k0 + t];
        uint32_t fa1 = a_hi[k0 + t];
        uint32_t fa2 = a_lo[k0 + t + 4];
        uint32_t fa3 = a_hi[k0 + t + 4];

        #pragma unroll
        for (int j = 0; j < 4; ++j) {
            int n = nbase + 8 * j + g;
            uint32_t b0 = Wb[t * WSTRIDE + n];
            uint32_t b1 = Wb[(t + 4) * WSTRIDE + n];
            mma_tf32(d[j], fa0, fa1, fa2, fa3, b0, b1);
        }
        __syncthreads();
    }

    // ---- epilogue: bias + relu into smem (overwrite As) ----
    #pragma unroll
    for (int j = 0; j < 4; ++j) {
        int col = nbase + 8 * j + 2 * t;
        float2 bb = __ldg(reinterpret_cast<const float2*>(b + col));
        float2 lo, hi;
        lo.x = fmaxf(d[j][0] + bb.x, 0.0f);
        lo.y = fmaxf(d[j][1] + bb.y, 0.0f);
        hi.x = fmaxf(d[j][2] + bb.x, 0.0f);
        hi.y = fmaxf(d[j][3] + bb.y, 0.0f);
        *reinterpret_cast<float2*>(&As[(mrow + g)     * ASTRIDE + col]) = lo;
        *reinterpret_cast<float2*>(&As[(mrow + g + 8) * ASTRIDE + col]) = hi;
    }
    __syncthreads();

    // ---- per-row L2 norm: warp w handles rows 2w, 2w+1 ----
    #pragma unroll
    for (int rr = 0; rr < 2; ++rr) {
        int row = warp * 2 + rr;
        float s = 0.0f;
        #pragma unroll
        for (int jj = 0; jj < 8; ++jj) {
            float v = As[row * ASTRIDE + lane + 32 * jj];
            s = fmaf(v, v, s);
        }
        #pragma unroll
        for (int o = 16; o > 0; o >>= 1)
            s += __shfl_xor_sync(0xffffffffu, s, o);
        if (lane == 0)
            invN[row] = 1.0f / fmaxf(sqrtf(s), 1e-12f);
    }
    __syncthreads();

    // ---- normalized streaming store ----
    float4* out4 = reinterpret_cast<float4*>(out);
    for (int i = tid; i < BM * (DDIM / 4); i += THREADS) {
        int r = i >> 6, c = i & 63;
        if (r < rows) {
            float4 v = *reinterpret_cast<const float4*>(&As[r * ASTRIDE + 4 * c]);
            float sc = invN[r];
            v.x *= sc; v.y *= sc; v.z *= sc; v.w *= sc;
            stg_stream(out4 + (long)(blockBase + r) * (DDIM / 4) + c, v);
        }
    }
}

// ---- Fallback: fused fp32 kernel (caps exceeded) ----
__global__ __launch_bounds__(THREADS, 2)
void gsage_fused_f32(const int*   __restrict__ node_idx,
                     const int*   __restrict__ neigh_idx,
                     const float* __restrict__ features,
                     const float* __restrict__ W,
                     const float* __restrict__ b,
                     float*       __restrict__ out,
                     int n_nodes, int n_samp)
{
    extern __shared__ char smem[];
    float*    As   = reinterpret_cast<float*>(smem);
    int*      idxS = reinterpret_cast<int*>(smem + AS_BYTES);
    uint32_t* Ws   = reinterpret_cast<uint32_t*>(smem + AS_BYTES);
    float*    invN = reinterpret_cast<float*>(smem + AS_BYTES + R2_BYTES);

    const int tid       = threadIdx.x;
    const int blockBase = blockIdx.x * BM;
    const int rows      = min(BM, n_nodes - blockBase);
    const int S         = n_samp + 1;

    for (int i = tid; i < rows * S; i += THREADS) {
        int n = i / S, s = i - n * S;
        int gn = blockBase + n;
        idxS[n * S + s] = (s == 0) ? ldg_stream(node_idx + gn)
                                   : ldg_stream(neigh_idx + (long)gn * n_samp + (s - 1));
    }
    __syncthreads();

    const float invS = 1.0f / (float)S;
    {
        const int c4 = tid & 63;
        const int n0 = (tid >> 6) * 4;
        const float4* F4 = reinterpret_cast<const float4*>(features);

        const bool v0 = (n0 + 0) < rows, v1 = (n0 + 1) < rows;
        const bool v2 = (n0 + 2) < rows, v3 = (n0 + 3) < rows;
        const int* ip0 = idxS + (v0 ? (n0 + 0) * S : 0);
        const int* ip1 = idxS + (v1 ? (n0 + 1) * S : 0);
        const int* ip2 = idxS + (v2 ? (n0 + 2) * S : 0);
        const int* ip3 = idxS + (v3 ? (n0 + 3) * S : 0);

        float4 a0 = {0,0,0,0}, a1 = {0,0,0,0}, a2 = {0,0,0,0}, a3 = {0,0,0,0};
        #pragma unroll 4
        for (int s = 0; s < S; ++s) {
            float4 t0 = __ldg(F4 + (long)ip0[s] * (DDIM/4) + c4);
            float4 t1 = __ldg(F4 + (long)ip1[s] * (DDIM/4) + c4);
            float4 t2 = __ldg(F4 + (long)ip2[s] * (DDIM/4) + c4);
            float4 t3 = __ldg(F4 + (long)ip3[s] * (DDIM/4) + c4);
            a0.x += t0.x; a0.y += t0.y; a0.z += t0.z; a0.w += t0.w;
            a1.x += t1.x; a1.y += t1.y; a1.z += t1.z; a1.w += t1.w;
            a2.x += t2.x; a2.y += t2.y; a2.z += t2.z; a2.w += t2.w;
            a3.x += t3.x; a3.y += t3.y; a3.z += t3.z; a3.w += t3.w;
        }
        const float m0 = v0 ? invS : 0.0f, m1 = v1 ? invS : 0.0f;
        const float m2 = v2 ? invS : 0.0f, m3 = v3 ? invS : 0.0f;
        uint4 u0 = { f2tf32(a0.x*m0), f2tf32(a0.y*m0), f2tf32(a0.z*m0), f2tf32(a0.w*m0) };
        uint4 u1 = { f2tf32(a1.x*m1), f2tf32(a1.y*m1), f2tf32(a1.z*m1), f2tf32(a1.w*m1) };
        uint4 u2 = { f2tf32(a2.x*m2), f2tf32(a2.y*m2), f2tf32(a2.z*m2), f2tf32(a2.w*m2) };
        uint4 u3 = { f2tf32(a3.x*m3), f2tf32(a3.y*m3), f2tf32(a3.z*m3), f2tf32(a3.w*m3) };
        *reinterpret_cast<uint4*>(&As[(n0 + 0) * ASTRIDE + 4 * c4]) = u0;
        *reinterpret_cast<uint4*>(&As[(n0 + 1) * ASTRIDE + 4 * c4]) = u1;
        *reinterpret_cast<uint4*>(&As[(n0 + 2) * ASTRIDE + 4 * c4]) = u2;
        *reinterpret_cast<uint4*>(&As[(n0 + 3) * ASTRIDE + 4 * c4]) = u3;
    }
    __syncthreads();

    const int lane = tid & 31, warp = tid >> 5;
    const int g    = lane >> 2, t = lane & 3;
    const int mrow  = (warp & 1) * 16;
    const int nbase = (warp >> 1) * 32;
    const int kk = tid >> 6;
    const int n4 = (tid & 63) * 4;

    float d[4][4];
    #pragma unroll
    for (int j = 0; j < 4; ++j)
        #pragma unroll
        for (int c = 0; c < 4; ++c) d[j][c] = 0.0f;

    const uint32_t* a_lo = reinterpret_cast<const uint32_t*>(As) + (mrow + g) * ASTRIDE;
    const uint32_t* a_hi = a_lo + 8 * ASTRIDE;

    {
        float4 w = *reinterpret_cast<const float4*>(&W[kk * DDIM + n4]);
        uint4 u = { f2tf32(w.x), f2tf32(w.y), f2tf32(w.z), f2tf32(w.w) };
        *reinterpret_cast<uint4*>(&Ws[kk * WSTRIDE + n4]) = u;
    }
    __syncthreads();

    for (int kc = 0; kc < DDIM / 8; ++kc) {
        const uint32_t* Wb = Ws + (kc & 1) * (8 * WSTRIDE);
        if (kc + 1 < DDIM / 8) {
            float4 w = *reinterpret_cast<const float4*>(
                           &W[((kc + 1) * 8 + kk) * DDIM + n4]);
            uint4 u = { f2tf32(w.x), f2tf32(w.y), f2tf32(w.z), f2tf32(w.w) };
            *reinterpret_cast<uint4*>(
                &Ws[((kc + 1) & 1) * (8 * WSTRIDE) + kk * WSTRIDE + n4]) = u;
        }
        const int k0 = kc * 8;
        uint32_t fa0 = a_lo[k0 + t];
        uint32_t fa1 = a_hi[k0 + t];
        uint32_t fa2 = a_lo[k0 + t + 4];
        uint32_t fa3 = a_hi[k0 + t + 4];
        #pragma unroll
        for (int j = 0; j < 4; ++j) {
            int n = nbase + 8 * j + g;
            uint32_t b0 = Wb[t * WSTRIDE + n];
            uint32_t b1 = Wb[(t + 4) * WSTRIDE + n];
            mma_tf32(d[j], fa0, fa1, fa2, fa3, b0, b1);
        }
        __syncthreads();
    }

    #pragma unroll
    for (int j = 0; j < 4; ++j) {
        int col = nbase + 8 * j + 2 * t;
        float2 bb = __ldg(reinterpret_cast<const float2*>(b + col));
        float2 lo, hi;
        lo.x = fmaxf(d[j][0] + bb.x, 0.0f);
        lo.y = fmaxf(d[j][1] + bb.y, 0.0f);
        hi.x = fmaxf(d[j][2] + bb.x, 0.0f);
        hi.y = fmaxf(d[j][3] + bb.y, 0.0f);
        *reinterpret_cast<float2*>(&As[(mrow + g)     * ASTRIDE + col]) = lo;
        *reinterpret_cast<float2*>(&As[(mrow + g + 8) * ASTRIDE + col]) = hi;
    }
    __syncthreads();

    #pragma unroll
    for (int rr = 0; rr < 2; ++rr) {
        int row = warp * 2 + rr;
        float s = 0.0f;
        #pragma unroll
        for (int jj = 0; jj < 8; ++jj) {
            float v = As[row * ASTRIDE + lane + 32 * jj];
            s = fmaf(v, v, s);
        }
        #pragma unroll
        for (int o = 16; o > 0; o >>= 1)
            s += __shfl_xor_sync(0xffffffffu, s, o);
        if (lane == 0)
            invN[row] = 1.0f / fmaxf(sqrtf(s), 1e-12f);
    }
    __syncthreads();

    float4* out4 = reinterpret_cast<float4*>(out);
    for (int i = tid; i < BM * (DDIM / 4); i += THREADS) {
        int r = i >> 6, c = i & 63;
        if (r < rows) {
            float4 v = *reinterpret_cast<const float4*>(&As[r * ASTRIDE + 4 * c]);
            float sc = invN[r];
            v.x *= sc; v.y *= sc; v.z *= sc; v.w *= sc;
            stg_stream(out4 + (long)(blockBase + r) * (DDIM / 4) + c, v);
        }
    }
}

extern "C" void kernel_launch(void* const* d_in, const int* in_sizes, int n_in,
                              void* d_out, int out_size)
{
    const int*   node_idx  = (const int*)  d_in[0];
    const int*   neigh_idx = (const int*)  d_in[1];
    const float* features  = (const float*)d_in[2];
    const float* W         = (const float*)d_in[3];
    const float* b         = (const float*)d_in[4];
    float*       out       = (float*)      d_out;

    const int n_nodes = in_sizes[0];
    const int n_samp  = in_sizes[1] / n_nodes;   // 32
    const int n_table = in_sizes[2] / DDIM;

    if (n_table <= NTAB_CAP && n_nodes <= NODE_CAP && n_samp + 1 <= MAX_S) {
        const int n_vec = n_table * 32;
        cvt_f16_kernel<<<3125, 512>>>(
            reinterpret_cast<const float4*>(features), n_vec);

        const int ggrid = (n_nodes + GW - 1) / GW;
        gather_kernel<<<ggrid, THREADS>>>(node_idx, neigh_idx, n_nodes, n_samp);

        cudaFuncSetAttribute(gemm_kernel,
                             cudaFuncAttributeMaxDynamicSharedMemorySize, SMEM_BYTES);
        const int mgrid = (n_nodes + BM - 1) / BM;
        gemm_kernel<<<mgrid, THREADS, SMEM_BYTES>>>(W, b, out, n_nodes);
    } else {
        cudaFuncSetAttribute(gsage_fused_f32,
                             cudaFuncAttributeMaxDynamicSharedMemorySize, SMEM_BYTES);
        const int grid = (n_nodes + BM - 1) / BM;
        gsage_fused_f32<<<grid, THREADS, SMEM_BYTES>>>(
            node_idx, neigh_idx, features, W, b, out, n_nodes, n_samp);
    }
}

// round 13
// speedup vs baseline: 1.1821x; 1.0375x over previous
#include <cuda_runtime.h>
#include <cuda_bf16.h>
#include <cuda_fp16.h>
#include <cstdint>

// Fused GraphSAGE layer, split pipeline (one graph):
//  K1 : feature table fp32 -> fp16 scratch (102MB; .wb writes keep it L2-hot)
//  K2a: gather+mean at high occupancy -> fp16 agg scratch (.cs, 25MB)
//  K2b: tf32 mma.sync GEMM (A tile converted fp16->tf32 at load), bias/relu,
//       shuffle row L2-norm, streaming store.
// Fallback: fused fp32 kernel when caps exceeded.

#define BM      32
#define DDIM    256
#define THREADS 512
#define MAX_S   40
#define ASTRIDE 260     // A tile row stride (words)
#define WSTRIDE 264     // W chunk row stride (words)
#define NTAB_CAP 200000 // fp16 table capacity (rows)
#define NODE_CAP 65536  // agg scratch capacity (rows)
#define GW      16      // nodes (warps) per gather block

#define AS_BYTES  (BM * ASTRIDE * 4)
#define WS_BYTES  (2 * 8 * WSTRIDE * 4)
#define IDX_BYTES (BM * MAX_S * 4)
#define R2_BYTES  (WS_BYTES > IDX_BYTES ? WS_BYTES : IDX_BYTES)
#define SMEM_BYTES (AS_BYTES + R2_BYTES + 128)

// fp16 feature table: 200000 x 256 x 2B = 102.4 MB (32 uint4 per row)
__device__ uint4 g_feat16[(size_t)NTAB_CAP * 32];
// fp16 agg scratch: 65536 x 256 x 2B = 32 MB (32 uint4 per row)
__device__ uint4 g_agg16[(size_t)NODE_CAP * 32];

__device__ __forceinline__ uint32_t f2tf32(float f) {
    uint32_t u;
    asm("cvt.rna.tf32.f32 %0, %1;" : "=r"(u) : "f"(f));
    return u;
}

__device__ __forceinline__ int ldg_stream(const int* p) {
    int v;
    asm("ld.global.cs.s32 %0, [%1];" : "=r"(v) : "l"(p));
    return v;
}

__device__ __forceinline__ float4 ldg_stream4(const float4* p) {
    float4 v;
    asm("ld.global.cs.v4.f32 {%0,%1,%2,%3}, [%4];"
        : "=f"(v.x), "=f"(v.y), "=f"(v.z), "=f"(v.w) : "l"(p));
    return v;
}

__device__ __forceinline__ uint4 ldg_stream_u4(const uint4* p) {
    uint4 v;
    asm("ld.global.cs.v4.b32 {%0,%1,%2,%3}, [%4];"
        : "=r"(v.x), "=r"(v.y), "=r"(v.z), "=r"(v.w) : "l"(p));
    return v;
}

__device__ __forceinline__ void stg_stream(float4* p, float4 v) {
    asm volatile("st.global.cs.v4.f32 [%0], {%1,%2,%3,%4};"
                 :: "l"(p), "f"(v.x), "f"(v.y), "f"(v.z), "f"(v.w));
}

__device__ __forceinline__ void stg_stream_u4(uint4* p, uint4 v) {
    asm volatile("st.global.cs.v4.b32 [%0], {%1,%2,%3,%4};"
                 :: "l"(p), "r"(v.x), "r"(v.y), "r"(v.z), "r"(v.w));
}

__device__ __forceinline__ void mma_tf32(float* d,
                                         uint32_t a0, uint32_t a1,
                                         uint32_t a2, uint32_t a3,
                                         uint32_t b0, uint32_t b1)
{
    asm("mma.sync.aligned.m16n8k8.row.col.f32.tf32.tf32.f32 "
        "{%0,%1,%2,%3}, {%4,%5,%6,%7}, {%8,%9}, {%0,%1,%2,%3};"
        : "+f"(d[0]), "+f"(d[1]), "+f"(d[2]), "+f"(d[3])
        : "r"(a0), "r"(a1), "r"(a2), "r"(a3), "r"(b0), "r"(b1));
}

// accumulate one fp16 row fragment (8 halves) into 8 float accumulators
__device__ __forceinline__ void acc_single(float* acc, uint4 x) {
    const __half2* hx = reinterpret_cast<const __half2*>(&x);
    #pragma unroll
    for (int j = 0; j < 4; ++j) {
        float2 f = __half22float2(hx[j]);
        acc[2*j]   += f.x;
        acc[2*j+1] += f.y;
    }
}

// ---- K1: fp32 -> fp16 table conversion ----
__global__ void cvt_f16_kernel(const float4* __restrict__ F4, int n_vec)
{
    int i      = blockIdx.x * blockDim.x + threadIdx.x;
    int stride = gridDim.x * blockDim.x;
    for (; i < n_vec; i += stride) {
        float4 f0 = ldg_stream4(F4 + 2 * (long)i);
        float4 f1 = ldg_stream4(F4 + 2 * (long)i + 1);
        __half2 h0 = __float22half2_rn(make_float2(f0.x, f0.y));
        __half2 h1 = __float22half2_rn(make_float2(f0.z, f0.w));
        __half2 h2 = __float22half2_rn(make_float2(f1.x, f1.y));
        __half2 h3 = __float22half2_rn(make_float2(f1.z, f1.w));
        uint4 u;
        u.x = *reinterpret_cast<uint32_t*>(&h0);
        u.y = *reinterpret_cast<uint32_t*>(&h1);
        u.z = *reinterpret_cast<uint32_t*>(&h2);
        u.w = *reinterpret_cast<uint32_t*>(&h3);
        g_feat16[i] = u;   // .wb: table resident in L2
    }
}

// ---- K2a: high-occupancy gather+mean -> fp16 agg scratch (.cs) ----
__global__ __launch_bounds__(THREADS, 3)
void gather_kernel(const int* __restrict__ node_idx,
                   const int* __restrict__ neigh_idx,
                   int n_nodes, int n_samp)
{
    __shared__ int idxS[GW * MAX_S];

    const int tid       = threadIdx.x;
    const int blockBase = blockIdx.x * GW;
    const int rows      = min(GW, n_nodes - blockBase);
    const int S         = n_samp + 1;

    for (int i = tid; i < rows * S; i += THREADS) {
        int n = i / S, s = i - n * S;
        int gn = blockBase + n;
        idxS[n * S + s] = (s == 0) ? ldg_stream(node_idx + gn)
                                   : ldg_stream(neigh_idx + (long)gn * n_samp + (s - 1));
    }
    __syncthreads();

    const int lane = tid & 31;
    const int w    = tid >> 5;          // warp = node within block
    if (w >= rows) return;              // no barriers after this point
    const int* ip = idxS + w * S;

    float acc[8];
    #pragma unroll
    for (int j = 0; j < 8; ++j) acc[j] = 0.0f;

    int s = 0;
    #pragma unroll 1
    for (; s + 4 <= S; s += 4) {        // 4 independent row loads in flight
        uint4 u0 = g_feat16[(long)ip[s + 0] * 32 + lane];
        uint4 u1 = g_feat16[(long)ip[s + 1] * 32 + lane];
        uint4 u2 = g_feat16[(long)ip[s + 2] * 32 + lane];
        uint4 u3 = g_feat16[(long)ip[s + 3] * 32 + lane];
        acc_single(acc, u0);
        acc_single(acc, u1);
        acc_single(acc, u2);
        acc_single(acc, u3);
    }
    for (; s < S; ++s) {
        uint4 u = g_feat16[(long)ip[s] * 32 + lane];
        acc_single(acc, u);
    }

    const float invS = 1.0f / (float)S;
    __half2 p0 = __floats2half2_rn(acc[0] * invS, acc[1] * invS);
    __half2 p1 = __floats2half2_rn(acc[2] * invS, acc[3] * invS);
    __half2 p2 = __floats2half2_rn(acc[4] * invS, acc[5] * invS);
    __half2 p3 = __floats2half2_rn(acc[6] * invS, acc[7] * invS);
    uint4 o;
    o.x = *reinterpret_cast<uint32_t*>(&p0);
    o.y = *reinterpret_cast<uint32_t*>(&p1);
    o.z = *reinterpret_cast<uint32_t*>(&p2);
    o.w = *reinterpret_cast<uint32_t*>(&p3);
    stg_stream_u4(g_agg16 + (size_t)(blockBase + w) * 32 + lane, o);
}

// ---- K2b: tf32 GEMM + epilogue (A from fp16 scratch) ----
__global__ __launch_bounds__(THREADS, 2)
void gemm_kernel(const float* __restrict__ W,
                 const float* __restrict__ b,
                 float*       __restrict__ out,
                 int n_nodes)
{
    extern __shared__ char smem[];
    float*    As   = reinterpret_cast<float*>(smem);               // [32][260]
    uint32_t* Ws   = reinterpret_cast<uint32_t*>(smem + AS_BYTES);
    float*    invN = reinterpret_cast<float*>(smem + AS_BYTES + R2_BYTES);

    const int tid       = threadIdx.x;
    const int blockBase = blockIdx.x * BM;
    const int rows      = min(BM, n_nodes - blockBase);

    // ---- load fp16 A tile, convert to tf32 bits, into padded smem ----
    const uint4* A4 = g_agg16 + (size_t)blockBase * 32;
    for (int i = tid; i < BM * 32; i += THREADS) {
        int r = i >> 5, c = i & 31;     // c -> k range 8c..8c+7
        uint4 u = ldg_stream_u4(A4 + i);
        const __half2* h = reinterpret_cast<const __half2*>(&u);
        uint4 w0, w1;
        float2 f0 = __half22float2(h[0]);
        float2 f1 = __half22float2(h[1]);
        float2 f2 = __half22float2(h[2]);
        float2 f3 = __half22float2(h[3]);
        w0.x = f2tf32(f0.x); w0.y = f2tf32(f0.y);
        w0.z = f2tf32(f1.x); w0.w = f2tf32(f1.y);
        w1.x = f2tf32(f2.x); w1.y = f2tf32(f2.y);
        w1.z = f2tf32(f3.x); w1.w = f2tf32(f3.y);
        uint32_t* dst = reinterpret_cast<uint32_t*>(&As[r * ASTRIDE + 8 * c]);
        *reinterpret_cast<uint4*>(dst)     = w0;
        *reinterpret_cast<uint4*>(dst + 4) = w1;
    }
    __syncthreads();

    // ---- tensor-core GEMM: tf32 m16n8k8, W staged via smem ----
    const int lane = tid & 31, warp = tid >> 5;
    const int g    = lane >> 2, t = lane & 3;
    const int mrow  = (warp & 1) * 16;
    const int nbase = (warp >> 1) * 32;

    const int kk = tid >> 6;
    const int n4 = (tid & 63) * 4;

    float d[4][4];
    #pragma unroll
    for (int j = 0; j < 4; ++j)
        #pragma unroll
        for (int c = 0; c < 4; ++c) d[j][c] = 0.0f;

    const uint32_t* a_lo = reinterpret_cast<const uint32_t*>(As) + (mrow + g) * ASTRIDE;
    const uint32_t* a_hi = a_lo + 8 * ASTRIDE;

    {
        float4 w = *reinterpret_cast<const float4*>(&W[kk * DDIM + n4]);
        uint4 u = { f2tf32(w.x), f2tf32(w.y), f2tf32(w.z), f2tf32(w.w) };
        *reinterpret_cast<uint4*>(&Ws[kk * WSTRIDE + n4]) = u;
    }
    __syncthreads();

    for (int kc = 0; kc < DDIM / 8; ++kc) {
        const uint32_t* Wb = Ws + (kc & 1) * (8 * WSTRIDE);

        if (kc + 1 < DDIM / 8) {
            float4 w = *reinterpret_cast<const float4*>(
                           &W[((kc + 1) * 8 + kk) * DDIM + n4]);
            uint4 u = { f2tf32(w.x), f2tf32(w.y), f2tf32(w.z), f2tf32(w.w) };
            *reinterpret_cast<uint4*>(
                &Ws[((kc + 1) & 1) * (8 * WSTRIDE) + kk * WSTRIDE + n4]) = u;
        }

        const int k0 = kc * 8;
        uint32_t fa0 = a_lo[k0 + t];
        uint32_t fa1 = a_hi[k0 + t];
        uint32_t fa2 = a_lo[k0 + t + 4];
        uint32_t fa3 = a_hi[k0 + t + 4];

        #pragma unroll
        for (int j = 0; j < 4; ++j) {
            int n = nbase + 8 * j + g;
            uint32_t b0 = Wb[t * WSTRIDE + n];
            uint32_t b1 = Wb[(t + 4) * WSTRIDE + n];
            mma_tf32(d[j], fa0, fa1, fa2, fa3, b0, b1);
        }
        __syncthreads();
    }

    // ---- epilogue: bias + relu into smem (overwrite As) ----
    #pragma unroll
    for (int j = 0; j < 4; ++j) {
        int col = nbase + 8 * j + 2 * t;
        float2 bb = __ldg(reinterpret_cast<const float2*>(b + col));
        float2 lo, hi;
        lo.x = fmaxf(d[j][0] + bb.x, 0.0f);
        lo.y = fmaxf(d[j][1] + bb.y, 0.0f);
        hi.x = fmaxf(d[j][2] + bb.x, 0.0f);
        hi.y = fmaxf(d[j][3] + bb.y, 0.0f);
        *reinterpret_cast<float2*>(&As[(mrow + g)     * ASTRIDE + col]) = lo;
        *reinterpret_cast<float2*>(&As[(mrow + g + 8) * ASTRIDE + col]) = hi;
    }
    __syncthreads();

    // ---- per-row L2 norm: warp w handles rows 2w, 2w+1 ----
    #pragma unroll
    for (int rr = 0; rr < 2; ++rr) {
        int row = warp * 2 + rr;
        float s = 0.0f;
        #pragma unroll
        for (int jj = 0; jj < 8; ++jj) {
            float v = As[row * ASTRIDE + lane + 32 * jj];
            s = fmaf(v, v, s);
        }
        #pragma unroll
        for (int o = 16; o > 0; o >>= 1)
            s += __shfl_xor_sync(0xffffffffu, s, o);
        if (lane == 0)
            invN[row] = 1.0f / fmaxf(sqrtf(s), 1e-12f);
    }
    __syncthreads();

    // ---- normalized streaming store ----
    float4* out4 = reinterpret_cast<float4*>(out);
    for (int i = tid; i < BM * (DDIM / 4); i += THREADS) {
        int r = i >> 6, c = i & 63;
        if (r < rows) {
            float4 v = *reinterpret_cast<const float4*>(&As[r * ASTRIDE + 4 * c]);
            float sc = invN[r];
            v.x *= sc; v.y *= sc; v.z *= sc; v.w *= sc;
            stg_stream(out4 + (long)(blockBase + r) * (DDIM / 4) + c, v);
        }
    }
}

// ---- Fallback: fused fp32 kernel (caps exceeded) ----
__global__ __launch_bounds__(THREADS, 2)
void gsage_fused_f32(const int*   __restrict__ node_idx,
                     const int*   __restrict__ neigh_idx,
                     const float* __restrict__ features,
                     const float* __restrict__ W,
                     const float* __restrict__ b,
                     float*       __restrict__ out,
                     int n_nodes, int n_samp)
{
    extern __shared__ char smem[];
    float*    As   = reinterpret_cast<float*>(smem);
    int*      idxS = reinterpret_cast<int*>(smem + AS_BYTES);
    uint32_t* Ws   = reinterpret_cast<uint32_t*>(smem + AS_BYTES);
    float*    invN = reinterpret_cast<float*>(smem + AS_BYTES + R2_BYTES);

    const int tid       = threadIdx.x;
    const int blockBase = blockIdx.x * BM;
    const int rows      = min(BM, n_nodes - blockBase);
    const int S         = n_samp + 1;

    for (int i = tid; i < rows * S; i += THREADS) {
        int n = i / S, s = i - n * S;
        int gn = blockBase + n;
        idxS[n * S + s] = (s == 0) ? ldg_stream(node_idx + gn)
                                   : ldg_stream(neigh_idx + (long)gn * n_samp + (s - 1));
    }
    __syncthreads();

    const float invS = 1.0f / (float)S;
    {
        const int c4 = tid & 63;
        const int n0 = (tid >> 6) * 4;
        const float4* F4 = reinterpret_cast<const float4*>(features);

        const bool v0 = (n0 + 0) < rows, v1 = (n0 + 1) < rows;
        const bool v2 = (n0 + 2) < rows, v3 = (n0 + 3) < rows;
        const int* ip0 = idxS + (v0 ? (n0 + 0) * S : 0);
        const int* ip1 = idxS + (v1 ? (n0 + 1) * S : 0);
        const int* ip2 = idxS + (v2 ? (n0 + 2) * S : 0);
        const int* ip3 = idxS + (v3 ? (n0 + 3) * S : 0);

        float4 a0 = {0,0,0,0}, a1 = {0,0,0,0}, a2 = {0,0,0,0}, a3 = {0,0,0,0};
        #pragma unroll 4
        for (int s = 0; s < S; ++s) {
            float4 t0 = __ldg(F4 + (long)ip0[s] * (DDIM/4) + c4);
            float4 t1 = __ldg(F4 + (long)ip1[s] * (DDIM/4) + c4);
            float4 t2 = __ldg(F4 + (long)ip2[s] * (DDIM/4) + c4);
            float4 t3 = __ldg(F4 + (long)ip3[s] * (DDIM/4) + c4);
            a0.x += t0.x; a0.y += t0.y; a0.z += t0.z; a0.w += t0.w;
            a1.x += t1.x; a1.y += t1.y; a1.z += t1.z; a1.w += t1.w;
            a2.x += t2.x; a2.y += t2.y; a2.z += t2.z; a2.w += t2.w;
            a3.x += t3.x; a3.y += t3.y; a3.z += t3.z; a3.w += t3.w;
        }
        const float m0 = v0 ? invS : 0.0f, m1 = v1 ? invS : 0.0f;
        const float m2 = v2 ? invS : 0.0f, m3 = v3 ? invS : 0.0f;
        uint4 u0 = { f2tf32(a0.x*m0), f2tf32(a0.y*m0), f2tf32(a0.z*m0), f2tf32(a0.w*m0) };
        uint4 u1 = { f2tf32(a1.x*m1), f2tf32(a1.y*m1), f2tf32(a1.z*m1), f2tf32(a1.w*m1) };
        uint4 u2 = { f2tf32(a2.x*m2), f2tf32(a2.y*m2), f2tf32(a2.z*m2), f2tf32(a2.w*m2) };
        uint4 u3 = { f2tf32(a3.x*m3), f2tf32(a3.y*m3), f2tf32(a3.z*m3), f2tf32(a3.w*m3) };
        *reinterpret_cast<uint4*>(&As[(n0 + 0) * ASTRIDE + 4 * c4]) = u0;
        *reinterpret_cast<uint4*>(&As[(n0 + 1) * ASTRIDE + 4 * c4]) = u1;
        *reinterpret_cast<uint4*>(&As[(n0 + 2) * ASTRIDE + 4 * c4]) = u2;
        *reinterpret_cast<uint4*>(&As[(n0 + 3) * ASTRIDE + 4 * c4]) = u3;
    }
    __syncthreads();

    const int lane = tid & 31, warp = tid >> 5;
    const int g    = lane >> 2, t = lane & 3;
    const int mrow  = (warp & 1) * 16;
    const int nbase = (warp >> 1) * 32;
    const int kk = tid >> 6;
    const int n4 = (tid & 63) * 4;

    float d[4][4];
    #pragma unroll
    for (int j = 0; j < 4; ++j)
        #pragma unroll
        for (int c = 0; c < 4; ++c) d[j][c] = 0.0f;

    const uint32_t* a_lo = reinterpret_cast<const uint32_t*>(As) + (mrow + g) * ASTRIDE;
    const uint32_t* a_hi = a_lo + 8 * ASTRIDE;

    {
        float4 w = *reinterpret_cast<const float4*>(&W[kk * DDIM + n4]);
        uint4 u = { f2tf32(w.x), f2tf32(w.y), f2tf32(w.z), f2tf32(w.w) };
        *reinterpret_cast<uint4*>(&Ws[kk * WSTRIDE + n4]) = u;
    }
    __syncthreads();

    for (int kc = 0; kc < DDIM / 8; ++kc) {
        const uint32_t* Wb = Ws + (kc & 1) * (8 * WSTRIDE);
        if (kc + 1 < DDIM / 8) {
            float4 w = *reinterpret_cast<const float4*>(
                           &W[((kc + 1) * 8 + kk) * DDIM + n4]);
            uint4 u = { f2tf32(w.x), f2tf32(w.y), f2tf32(w.z), f2tf32(w.w) };
            *reinterpret_cast<uint4*>(
                &Ws[((kc + 1) & 1) * (8 * WSTRIDE) + kk * WSTRIDE + n4]) = u;
        }
        const int k0 = kc * 8;
        uint32_t fa0 = a_lo[k0 + t];
        uint32_t fa1 = a_hi[k0 + t];
        uint32_t fa2 = a_lo[k0 + t + 4];
        uint32_t fa3 = a_hi[k0 + t + 4];
        #pragma unroll
        for (int j = 0; j < 4; ++j) {
            int n = nbase + 8 * j + g;
            uint32_t b0 = Wb[t * WSTRIDE + n];
            uint32_t b1 = Wb[(t + 4) * WSTRIDE + n];
            mma_tf32(d[j], fa0, fa1, fa2, fa3, b0, b1);
        }
        __syncthreads();
    }

    #pragma unroll
    for (int j = 0; j < 4; ++j) {
        int col = nbase + 8 * j + 2 * t;
        float2 bb = __ldg(reinterpret_cast<const float2*>(b + col));
        float2 lo, hi;
        lo.x = fmaxf(d[j][0] + bb.x, 0.0f);
        lo.y = fmaxf(d[j][1] + bb.y, 0.0f);
        hi.x = fmaxf(d[j][2] + bb.x, 0.0f);
        hi.y = fmaxf(d[j][3] + bb.y, 0.0f);
        *reinterpret_cast<float2*>(&As[(mrow + g)     * ASTRIDE + col]) = lo;
        *reinterpret_cast<float2*>(&As[(mrow + g + 8) * ASTRIDE + col]) = hi;
    }
    __syncthreads();

    #pragma unroll
    for (int rr = 0; rr < 2; ++rr) {
        int row = warp * 2 + rr;
        float s = 0.0f;
        #pragma unroll
        for (int jj = 0; jj < 8; ++jj) {
            float v = As[row * ASTRIDE + lane + 32 * jj];
            s = fmaf(v, v, s);
        }
        #pragma unroll
        for (int o = 16; o > 0; o >>= 1)
            s += __shfl_xor_sync(0xffffffffu, s, o);
        if (lane == 0)
            invN[row] = 1.0f / fmaxf(sqrtf(s), 1e-12f);
    }
    __syncthreads();

    float4* out4 = reinterpret_cast<float4*>(out);
    for (int i = tid; i < BM * (DDIM / 4); i += THREADS) {
        int r = i >> 6, c = i & 63;
        if (r < rows) {
            float4 v = *reinterpret_cast<const float4*>(&As[r * ASTRIDE + 4 * c]);
            float sc = invN[r];
            v.x *= sc; v.y *= sc; v.z *= sc; v.w *= sc;
            stg_stream(out4 + (long)(blockBase + r) * (DDIM / 4) + c, v);
        }
    }
}

extern "C" void kernel_launch(void* const* d_in, const int* in_sizes, int n_in,
                              void* d_out, int out_size)
{
    const int*   node_idx  = (const int*)  d_in[0];
    const int*   neigh_idx = (const int*)  d_in[1];
    const float* features  = (const float*)d_in[2];
    const float* W         = (const float*)d_in[3];
    const float* b         = (const float*)d_in[4];
    float*       out       = (float*)      d_out;

    const int n_nodes = in_sizes[0];
    const int n_samp  = in_sizes[1] / n_nodes;   // 32
    const int n_table = in_sizes[2] / DDIM;

    if (n_table <= NTAB_CAP && n_nodes <= NODE_CAP && n_samp + 1 <= MAX_S) {
        const int n_vec = n_table * 32;
        cvt_f16_kernel<<<3125, 512>>>(
            reinterpret_cast<const float4*>(features), n_vec);

        const int ggrid = (n_nodes + GW - 1) / GW;
        gather_kernel<<<ggrid, THREADS>>>(node_idx, neigh_idx, n_nodes, n_samp);

        cudaFuncSetAttribute(gemm_kernel,
                             cudaFuncAttributeMaxDynamicSharedMemorySize, SMEM_BYTES);
        const int mgrid = (n_nodes + BM - 1) / BM;
        gemm_kernel<<<mgrid, THREADS, SMEM_BYTES>>>(W, b, out, n_nodes);
    } else {
        cudaFuncSetAttribute(gsage_fused_f32,
                             cudaFuncAttributeMaxDynamicSharedMemorySize, SMEM_BYTES);
        const int grid = (n_nodes + BM - 1) / BM;
        gsage_fused_f32<<<grid, THREADS, SMEM_BYTES>>>(
            node_idx, neigh_idx, features, W, b, out, n_nodes, n_samp);
    }
}

// round 14
// speedup vs baseline: 1.4367x; 1.2154x over previous
#include <cuda_runtime.h>
#include <cuda_bf16.h>
#include <cuda_fp16.h>
#include <cstdint>

// Fused GraphSAGE layer, split pipeline (one graph):
//  K1 : feature table fp32 -> fp16 scratch (102MB; .wb keeps it L2-hot)
//  K1c: W fp32 -> fp16 TRANSPOSED scratch (128KB, n-major)
//  K2a: gather+mean at high occupancy -> fp16 agg scratch (.cs)
//  K2b: PERSISTENT fp16 m16n8k16 GEMM: whole W in smem (staged once/block),
//       barrier-free mainloop, bias/relu, shuffle row L2-norm, streaming store.
// Fallback: fused fp32 tf32 kernel when caps exceeded.

#define BM      32
#define DDIM    256
#define THREADS 512
#define MAX_S   40
#define ASTRIDE 260     // fallback A tile row stride (words)
#define WSTRIDE 264     // fallback W chunk row stride (words)
#define KH      264     // fp16 row stride (halves) for persistent gemm smem
#define NTAB_CAP 200000
#define NODE_CAP 65536
#define GW      16      // nodes (warps) per gather block

// fallback-kernel smem
#define AS_BYTES  (BM * ASTRIDE * 4)
#define WS_BYTES  (2 * 8 * WSTRIDE * 4)
#define IDX_BYTES (BM * MAX_S * 4)
#define R2_BYTES  (WS_BYTES > IDX_BYTES ? WS_BYTES : IDX_BYTES)
#define SMEM_BYTES (AS_BYTES + R2_BYTES + 128)

// persistent-gemm smem
#define WN_BYTES   (DDIM * KH * 2)        // 135168
#define A16_BYTES  (BM * KH * 2)          // 16896
#define OUT_BYTES  (BM * ASTRIDE * 4)     // 33280
#define PG_SMEM    (WN_BYTES + A16_BYTES + OUT_BYTES + 128)

// fp16 feature table: 200000 x 256 x 2B = 102.4 MB (32 uint4 per row)
__device__ uint4 g_feat16[(size_t)NTAB_CAP * 32];
// fp16 agg scratch: 65536 x 256 x 2B = 32 MB (32 uint4 per row)
__device__ uint4 g_agg16[(size_t)NODE_CAP * 32];
// fp16 W transposed (n-major): 256 x 256 x 2B = 128 KB
__device__ uint4 g_w16t[DDIM * DDIM / 8];

__device__ __forceinline__ uint32_t f2tf32(float f) {
    uint32_t u;
    asm("cvt.rna.tf32.f32 %0, %1;" : "=r"(u) : "f"(f));
    return u;
}

__device__ __forceinline__ int ldg_stream(const int* p) {
    int v;
    asm("ld.global.cs.s32 %0, [%1];" : "=r"(v) : "l"(p));
    return v;
}

__device__ __forceinline__ float4 ldg_stream4(const float4* p) {
    float4 v;
    asm("ld.global.cs.v4.f32 {%0,%1,%2,%3}, [%4];"
        : "=f"(v.x), "=f"(v.y), "=f"(v.z), "=f"(v.w) : "l"(p));
    return v;
}

__device__ __forceinline__ uint4 ldg_stream_u4(const uint4* p) {
    uint4 v;
    asm("ld.global.cs.v4.b32 {%0,%1,%2,%3}, [%4];"
        : "=r"(v.x), "=r"(v.y), "=r"(v.z), "=r"(v.w) : "l"(p));
    return v;
}

__device__ __forceinline__ void stg_stream(float4* p, float4 v) {
    asm volatile("st.global.cs.v4.f32 [%0], {%1,%2,%3,%4};"
                 :: "l"(p), "f"(v.x), "f"(v.y), "f"(v.z), "f"(v.w));
}

__device__ __forceinline__ void stg_stream_u4(uint4* p, uint4 v) {
    asm volatile("st.global.cs.v4.b32 [%0], {%1,%2,%3,%4};"
                 :: "l"(p), "r"(v.x), "r"(v.y), "r"(v.z), "r"(v.w));
}

__device__ __forceinline__ void mma_tf32(float* d,
                                         uint32_t a0, uint32_t a1,
                                         uint32_t a2, uint32_t a3,
                                         uint32_t b0, uint32_t b1)
{
    asm("mma.sync.aligned.m16n8k8.row.col.f32.tf32.tf32.f32 "
        "{%0,%1,%2,%3}, {%4,%5,%6,%7}, {%8,%9}, {%0,%1,%2,%3};"
        : "+f"(d[0]), "+f"(d[1]), "+f"(d[2]), "+f"(d[3])
        : "r"(a0), "r"(a1), "r"(a2), "r"(a3), "r"(b0), "r"(b1));
}

__device__ __forceinline__ void mma_f16(float* d,
                                        uint32_t a0, uint32_t a1,
                                        uint32_t a2, uint32_t a3,
                                        uint32_t b0, uint32_t b1)
{
    asm("mma.sync.aligned.m16n8k16.row.col.f32.f16.f16.f32 "
        "{%0,%1,%2,%3}, {%4,%5,%6,%7}, {%8,%9}, {%0,%1,%2,%3};"
        : "+f"(d[0]), "+f"(d[1]), "+f"(d[2]), "+f"(d[3])
        : "r"(a0), "r"(a1), "r"(a2), "r"(a3), "r"(b0), "r"(b1));
}

// accumulate one fp16 row fragment (8 halves) into 8 float accumulators
__device__ __forceinline__ void acc_single(float* acc, uint4 x) {
    const __half2* hx = reinterpret_cast<const __half2*>(&x);
    #pragma unroll
    for (int j = 0; j < 4; ++j) {
        float2 f = __half22float2(hx[j]);
        acc[2*j]   += f.x;
        acc[2*j+1] += f.y;
    }
}

// ---- K1: fp32 -> fp16 table conversion ----
__global__ void cvt_f16_kernel(const float4* __restrict__ F4, int n_vec)
{
    int i      = blockIdx.x * blockDim.x + threadIdx.x;
    int stride = gridDim.x * blockDim.x;
    for (; i < n_vec; i += stride) {
        float4 f0 = ldg_stream4(F4 + 2 * (long)i);
        float4 f1 = ldg_stream4(F4 + 2 * (long)i + 1);
        __half2 h0 = __float22half2_rn(make_float2(f0.x, f0.y));
        __half2 h1 = __float22half2_rn(make_float2(f0.z, f0.w));
        __half2 h2 = __float22half2_rn(make_float2(f1.x, f1.y));
        __half2 h3 = __float22half2_rn(make_float2(f1.z, f1.w));
        uint4 u;
        u.x = *reinterpret_cast<uint32_t*>(&h0);
        u.y = *reinterpret_cast<uint32_t*>(&h1);
        u.z = *reinterpret_cast<uint32_t*>(&h2);
        u.w = *reinterpret_cast<uint32_t*>(&h3);
        g_feat16[i] = u;
    }
}

// ---- K1c: W fp32 [k][n] -> fp16 transposed [n][k] ----
__global__ void cvt_w16_kernel(const float* __restrict__ W)
{
    int k = blockIdx.x;          // 256 blocks
    int n = threadIdx.x;         // 256 threads
    float w = W[k * DDIM + n];
    reinterpret_cast<__half*>(g_w16t)[n * DDIM + k] = __float2half_rn(w);
}

// ---- K2a: high-occupancy gather+mean -> fp16 agg scratch (.cs) ----
__global__ __launch_bounds__(THREADS, 3)
void gather_kernel(const int* __restrict__ node_idx,
                   const int* __restrict__ neigh_idx,
                   int n_nodes, int n_samp)
{
    __shared__ int idxS[GW * MAX_S];

    const int tid       = threadIdx.x;
    const int blockBase = blockIdx.x * GW;
    const int rows      = min(GW, n_nodes - blockBase);
    const int S         = n_samp + 1;

    for (int i = tid; i < rows * S; i += THREADS) {
        int n = i / S, s = i - n * S;
        int gn = blockBase + n;
        idxS[n * S + s] = (s == 0) ? ldg_stream(node_idx + gn)
                                   : ldg_stream(neigh_idx + (long)gn * n_samp + (s - 1));
    }
    __syncthreads();

    const int lane = tid & 31;
    const int w    = tid >> 5;
    if (w >= rows) return;
    const int* ip = idxS + w * S;

    float acc[8];
    #pragma unroll
    for (int j = 0; j < 8; ++j) acc[j] = 0.0f;

    int s = 0;
    #pragma unroll 1
    for (; s + 4 <= S; s += 4) {
        uint4 u0 = g_feat16[(long)ip[s + 0] * 32 + lane];
        uint4 u1 = g_feat16[(long)ip[s + 1] * 32 + lane];
        uint4 u2 = g_feat16[(long)ip[s + 2] * 32 + lane];
        uint4 u3 = g_feat16[(long)ip[s + 3] * 32 + lane];
        acc_single(acc, u0);
        acc_single(acc, u1);
        acc_single(acc, u2);
        acc_single(acc, u3);
    }
    for (; s < S; ++s) {
        uint4 u = g_feat16[(long)ip[s] * 32 + lane];
        acc_single(acc, u);
    }

    const float invS = 1.0f / (float)S;
    __half2 p0 = __floats2half2_rn(acc[0] * invS, acc[1] * invS);
    __half2 p1 = __floats2half2_rn(acc[2] * invS, acc[3] * invS);
    __half2 p2 = __floats2half2_rn(acc[4] * invS, acc[5] * invS);
    __half2 p3 = __floats2half2_rn(acc[6] * invS, acc[7] * invS);
    uint4 o;
    o.x = *reinterpret_cast<uint32_t*>(&p0);
    o.y = *reinterpret_cast<uint32_t*>(&p1);
    o.z = *reinterpret_cast<uint32_t*>(&p2);
    o.w = *reinterpret_cast<uint32_t*>(&p3);
    stg_stream_u4(g_agg16 + (size_t)(blockBase + w) * 32 + lane, o);
}

// ---- K2b: persistent fp16 GEMM + epilogue ----
__global__ __launch_bounds__(THREADS, 1)
void gemm_kernel(const float* __restrict__ b,
                 float*       __restrict__ out,
                 int n_nodes, int ntiles)
{
    extern __shared__ char smem[];
    __half* Wn  = reinterpret_cast<__half*>(smem);                 // [256][KH]
    __half* A16 = reinterpret_cast<__half*>(smem + WN_BYTES);      // [32][KH]
    float*  OUT = reinterpret_cast<float*>(smem + WN_BYTES + A16_BYTES); // [32][260]
    float*  invN = reinterpret_cast<float*>(smem + WN_BYTES + A16_BYTES + OUT_BYTES);

    const int tid  = threadIdx.x;
    const int lane = tid & 31, warp = tid >> 5;
    const int g    = lane >> 2, t = lane & 3;
    const int mrow  = (warp & 1) * 16;
    const int nbase = (warp >> 1) * 32;

    // ---- stage full W (fp16, n-major) once ----
    for (int i = tid; i < DDIM * 32; i += THREADS) {
        int n = i >> 5, c = i & 31;
        *reinterpret_cast<uint4*>(Wn + n * KH + c * 8) = g_w16t[i];
    }

    // hoist bias
    float2 bb[4];
    #pragma unroll
    for (int j = 0; j < 4; ++j)
        bb[j] = __ldg(reinterpret_cast<const float2*>(b + nbase + 8 * j + 2 * t));

    float4* out4 = reinterpret_cast<float4*>(out);

    for (int tile = blockIdx.x; tile < ntiles; tile += gridDim.x) {
        const int blockBase = tile * BM;
        const int rows      = min(BM, n_nodes - blockBase);

        // ---- load fp16 A tile (raw copy) ----
        __syncthreads();   // previous tile fully consumed (OUT/A16 reads done)
        const uint4* A4 = g_agg16 + (size_t)blockBase * 32;
        for (int i = tid; i < BM * 32; i += THREADS) {
            int r = i >> 5, c = i & 31;
            *reinterpret_cast<uint4*>(A16 + r * KH + c * 8) = ldg_stream_u4(A4 + i);
        }
        __syncthreads();

        // ---- barrier-free fp16 mainloop: 16 k-steps x 4 n-tiles ----
        float d[4][4];
        #pragma unroll
        for (int j = 0; j < 4; ++j)
            #pragma unroll
            for (int c = 0; c < 4; ++c) d[j][c] = 0.0f;

        const __half* a_lo = A16 + (mrow + g) * KH;
        const __half* a_hi = a_lo + 8 * KH;

        #pragma unroll 4
        for (int k0 = 0; k0 < DDIM; k0 += 16) {
            uint32_t fa0 = *reinterpret_cast<const uint32_t*>(a_lo + k0 + 2 * t);
            uint32_t fa1 = *reinterpret_cast<const uint32_t*>(a_hi + k0 + 2 * t);
            uint32_t fa2 = *reinterpret_cast<const uint32_t*>(a_lo + k0 + 8 + 2 * t);
            uint32_t fa3 = *reinterpret_cast<const uint32_t*>(a_hi + k0 + 8 + 2 * t);

            #pragma unroll
            for (int j = 0; j < 4; ++j) {
                const __half* wrow = Wn + (nbase + 8 * j + g) * KH;
                uint32_t b0 = *reinterpret_cast<const uint32_t*>(wrow + k0 + 2 * t);
                uint32_t b1 = *reinterpret_cast<const uint32_t*>(wrow + k0 + 8 + 2 * t);
                mma_f16(d[j], fa0, fa1, fa2, fa3, b0, b1);
            }
        }

        // ---- epilogue: bias + relu into OUT ----
        #pragma unroll
        for (int j = 0; j < 4; ++j) {
            int col = nbase + 8 * j + 2 * t;
            float2 lo, hi;
            lo.x = fmaxf(d[j][0] + bb[j].x, 0.0f);
            lo.y = fmaxf(d[j][1] + bb[j].y, 0.0f);
            hi.x = fmaxf(d[j][2] + bb[j].x, 0.0f);
            hi.y = fmaxf(d[j][3] + bb[j].y, 0.0f);
            *reinterpret_cast<float2*>(&OUT[(mrow + g)     * ASTRIDE + col]) = lo;
            *reinterpret_cast<float2*>(&OUT[(mrow + g + 8) * ASTRIDE + col]) = hi;
        }
        __syncthreads();

        // ---- per-row L2 norm: warp w handles rows 2w, 2w+1 ----
        #pragma unroll
        for (int rr = 0; rr < 2; ++rr) {
            int row = warp * 2 + rr;
            float s = 0.0f;
            #pragma unroll
            for (int jj = 0; jj < 8; ++jj) {
                float v = OUT[row * ASTRIDE + lane + 32 * jj];
                s = fmaf(v, v, s);
            }
            #pragma unroll
            for (int o = 16; o > 0; o >>= 1)
                s += __shfl_xor_sync(0xffffffffu, s, o);
            if (lane == 0)
                invN[row] = 1.0f / fmaxf(sqrtf(s), 1e-12f);
        }
        __syncthreads();

        // ---- normalized streaming store ----
        for (int i = tid; i < BM * (DDIM / 4); i += THREADS) {
            int r = i >> 6, c = i & 63;
            if (r < rows) {
                float4 v = *reinterpret_cast<const float4*>(&OUT[r * ASTRIDE + 4 * c]);
                float sc = invN[r];
                v.x *= sc; v.y *= sc; v.z *= sc; v.w *= sc;
                stg_stream(out4 + (long)(blockBase + r) * (DDIM / 4) + c, v);
            }
        }
    }
}

// ---- Fallback: fused fp32/tf32 kernel (caps exceeded) ----
__global__ __launch_bounds__(THREADS, 2)
void gsage_fused_f32(const int*   __restrict__ node_idx,
                     const int*   __restrict__ neigh_idx,
                     const float* __restrict__ features,
                     const float* __restrict__ W,
                     const float* __restrict__ b,
                     float*       __restrict__ out,
                     int n_nodes, int n_samp)
{
    extern __shared__ char smem[];
    float*    As   = reinterpret_cast<float*>(smem);
    int*      idxS = reinterpret_cast<int*>(smem + AS_BYTES);
    uint32_t* Ws   = reinterpret_cast<uint32_t*>(smem + AS_BYTES);
    float*    invN = reinterpret_cast<float*>(smem + AS_BYTES + R2_BYTES);

    const int tid       = threadIdx.x;
    const int blockBase = blockIdx.x * BM;
    const int rows      = min(BM, n_nodes - blockBase);
    const int S         = n_samp + 1;

    for (int i = tid; i < rows * S; i += THREADS) {
        int n = i / S, s = i - n * S;
        int gn = blockBase + n;
        idxS[n * S + s] = (s == 0) ? ldg_stream(node_idx + gn)
                                   : ldg_stream(neigh_idx + (long)gn * n_samp + (s - 1));
    }
    __syncthreads();

    const float invS = 1.0f / (float)S;
    {
        const int c4 = tid & 63;
        const int n0 = (tid >> 6) * 4;
        const float4* F4 = reinterpret_cast<const float4*>(features);

        const bool v0 = (n0 + 0) < rows, v1 = (n0 + 1) < rows;
        const bool v2 = (n0 + 2) < rows, v3 = (n0 + 3) < rows;
        const int* ip0 = idxS + (v0 ? (n0 + 0) * S : 0);
        const int* ip1 = idxS + (v1 ? (n0 + 1) * S : 0);
        const int* ip2 = idxS + (v2 ? (n0 + 2) * S : 0);
        const int* ip3 = idxS + (v3 ? (n0 + 3) * S : 0);

        float4 a0 = {0,0,0,0}, a1 = {0,0,0,0}, a2 = {0,0,0,0}, a3 = {0,0,0,0};
        #pragma unroll 4
        for (int s = 0; s < S; ++s) {
            float4 t0 = __ldg(F4 + (long)ip0[s] * (DDIM/4) + c4);
            float4 t1 = __ldg(F4 + (long)ip1[s] * (DDIM/4) + c4);
            float4 t2 = __ldg(F4 + (long)ip2[s] * (DDIM/4) + c4);
            float4 t3 = __ldg(F4 + (long)ip3[s] * (DDIM/4) + c4);
            a0.x += t0.x; a0.y += t0.y; a0.z += t0.z; a0.w += t0.w;
            a1.x += t1.x; a1.y += t1.y; a1.z += t1.z; a1.w += t1.w;
            a2.x += t2.x; a2.y += t2.y; a2.z += t2.z; a2.w += t2.w;
            a3.x += t3.x; a3.y += t3.y; a3.z += t3.z; a3.w += t3.w;
        }
        const float m0 = v0 ? invS : 0.0f, m1 = v1 ? invS : 0.0f;
        const float m2 = v2 ? invS : 0.0f, m3 = v3 ? invS : 0.0f;
        uint4 u0 = { f2tf32(a0.x*m0), f2tf32(a0.y*m0), f2tf32(a0.z*m0), f2tf32(a0.w*m0) };
        uint4 u1 = { f2tf32(a1.x*m1), f2tf32(a1.y*m1), f2tf32(a1.z*m1), f2tf32(a1.w*m1) };
        uint4 u2 = { f2tf32(a2.x*m2), f2tf32(a2.y*m2), f2tf32(a2.z*m2), f2tf32(a2.w*m2) };
        uint4 u3 = { f2tf32(a3.x*m3), f2tf32(a3.y*m3), f2tf32(a3.z*m3), f2tf32(a3.w*m3) };
        *reinterpret_cast<uint4*>(&As[(n0 + 0) * ASTRIDE + 4 * c4]) = u0;
        *reinterpret_cast<uint4*>(&As[(n0 + 1) * ASTRIDE + 4 * c4]) = u1;
        *reinterpret_cast<uint4*>(&As[(n0 + 2) * ASTRIDE + 4 * c4]) = u2;
        *reinterpret_cast<uint4*>(&As[(n0 + 3) * ASTRIDE + 4 * c4]) = u3;
    }
    __syncthreads();

    const int lane = tid & 31, warp = tid >> 5;
    const int g    = lane >> 2, t = lane & 3;
    const int mrow  = (warp & 1) * 16;
    const int nbase = (warp >> 1) * 32;
    const int kk = tid >> 6;
    const int n4 = (tid & 63) * 4;

    float d[4][4];
    #pragma unroll
    for (int j = 0; j < 4; ++j)
        #pragma unroll
        for (int c = 0; c < 4; ++c) d[j][c] = 0.0f;

    const uint32_t* a_lo = reinterpret_cast<const uint32_t*>(As) + (mrow + g) * ASTRIDE;
    const uint32_t* a_hi = a_lo + 8 * ASTRIDE;

    {
        float4 w = *reinterpret_cast<const float4*>(&W[kk * DDIM + n4]);
        uint4 u = { f2tf32(w.x), f2tf32(w.y), f2tf32(w.z), f2tf32(w.w) };
        *reinterpret_cast<uint4*>(&Ws[kk * WSTRIDE + n4]) = u;
    }
    __syncthreads();

    for (int kc = 0; kc < DDIM / 8; ++kc) {
        const uint32_t* Wb = Ws + (kc & 1) * (8 * WSTRIDE);
        if (kc + 1 < DDIM / 8) {
            float4 w = *reinterpret_cast<const float4*>(
                           &W[((kc + 1) * 8 + kk) * DDIM + n4]);
            uint4 u = { f2tf32(w.x), f2tf32(w.y), f2tf32(w.z), f2tf32(w.w) };
            *reinterpret_cast<uint4*>(
                &Ws[((kc + 1) & 1) * (8 * WSTRIDE) + kk * WSTRIDE + n4]) = u;
        }
        const int k0 = kc * 8;
        uint32_t fa0 = a_lo[k0 + t];
        uint32_t fa1 = a_hi[k0 + t];
        uint32_t fa2 = a_lo[k0 + t + 4];
        uint32_t fa3 = a_hi[k0 + t + 4];
        #pragma unroll
        for (int j = 0; j < 4; ++j) {
            int n = nbase + 8 * j + g;
            uint32_t b0 = Wb[t * WSTRIDE + n];
            uint32_t b1 = Wb[(t + 4) * WSTRIDE + n];
            mma_tf32(d[j], fa0, fa1, fa2, fa3, b0, b1);
        }
        __syncthreads();
    }

    #pragma unroll
    for (int j = 0; j < 4; ++j) {
        int col = nbase + 8 * j + 2 * t;
        float2 bbf = __ldg(reinterpret_cast<const float2*>(b + col));
        float2 lo, hi;
        lo.x = fmaxf(d[j][0] + bbf.x, 0.0f);
        lo.y = fmaxf(d[j][1] + bbf.y, 0.0f);
        hi.x = fmaxf(d[j][2] + bbf.x, 0.0f);
        hi.y = fmaxf(d[j][3] + bbf.y, 0.0f);
        *reinterpret_cast<float2*>(&As[(mrow + g)     * ASTRIDE + col]) = lo;
        *reinterpret_cast<float2*>(&As[(mrow + g + 8) * ASTRIDE + col]) = hi;
    }
    __syncthreads();

    #pragma unroll
    for (int rr = 0; rr < 2; ++rr) {
        int row = warp * 2 + rr;
        float s = 0.0f;
        #pragma unroll
        for (int jj = 0; jj < 8; ++jj) {
            float v = As[row * ASTRIDE + lane + 32 * jj];
            s = fmaf(v, v, s);
        }
        #pragma unroll
        for (int o = 16; o > 0; o >>= 1)
            s += __shfl_xor_sync(0xffffffffu, s, o);
        if (lane == 0)
            invN[row] = 1.0f / fmaxf(sqrtf(s), 1e-12f);
    }
    __syncthreads();

    float4* out4 = reinterpret_cast<float4*>(out);
    for (int i = tid; i < BM * (DDIM / 4); i += THREADS) {
        int r = i >> 6, c = i & 63;
        if (r < rows) {
            float4 v = *reinterpret_cast<const float4*>(&As[r * ASTRIDE + 4 * c]);
            float sc = invN[r];
            v.x *= sc; v.y *= sc; v.z *= sc; v.w *= sc;
            stg_stream(out4 + (long)(blockBase + r) * (DDIM / 4) + c, v);
        }
    }
}

extern "C" void kernel_launch(void* const* d_in, const int* in_sizes, int n_in,
                              void* d_out, int out_size)
{
    const int*   node_idx  = (const int*)  d_in[0];
    const int*   neigh_idx = (const int*)  d_in[1];
    const float* features  = (const float*)d_in[2];
    const float* W         = (const float*)d_in[3];
    const float* b         = (const float*)d_in[4];
    float*       out       = (float*)      d_out;

    const int n_nodes = in_sizes[0];
    const int n_samp  = in_sizes[1] / n_nodes;   // 32
    const int n_table = in_sizes[2] / DDIM;
    const int ntiles  = (n_nodes + BM - 1) / BM;

    if (n_table <= NTAB_CAP && n_nodes <= NODE_CAP && n_samp + 1 <= MAX_S) {
        const int n_vec = n_table * 32;
        cvt_f16_kernel<<<3125, 512>>>(
            reinterpret_cast<const float4*>(features), n_vec);
        cvt_w16_kernel<<<DDIM, DDIM>>>(W);

        const int ggrid = (n_nodes + GW - 1) / GW;
        gather_kernel<<<ggrid, THREADS>>>(node_idx, neigh_idx, n_nodes, n_samp);

        cudaFuncSetAttribute(gemm_kernel,
                             cudaFuncAttributeMaxDynamicSharedMemorySize, PG_SMEM);
        const int mgrid = (ntiles < 148) ? ntiles : 148;
        gemm_kernel<<<mgrid, THREADS, PG_SMEM>>>(b, out, n_nodes, ntiles);
    } else {
        cudaFuncSetAttribute(gsage_fused_f32,
                             cudaFuncAttributeMaxDynamicSharedMemorySize, SMEM_BYTES);
        const int grid = (n_nodes + BM - 1) / BM;
        gsage_fused_f32<<<grid, THREADS, SMEM_BYTES>>>(
            node_idx, neigh_idx, features, W, b, out, n_nodes, n_samp);
    }
}

// round 15
// speedup vs baseline: 1.4455x; 1.0062x over previous
#include <cuda_runtime.h>
#include <cuda_bf16.h>
#include <cuda_fp16.h>
#include <cstdint>

// Fused GraphSAGE layer, split pipeline (one graph):
//  K1 : feature table fp32 -> fp16 scratch (102MB; .wb keeps it L2-hot)
//  K1c: W fp32 -> fp16 TRANSPOSED scratch (128KB, n-major)
//  K2a: gather+mean at high occupancy -> fp16 agg scratch (.cs)
//  K2b: PERSISTENT fp16 m16n8k16 GEMM: whole W in smem, ldmatrix fragment
//       loads (3 LDSM.x4 per k-step), bias/relu, row L2-norm, streaming store.
// Fallback: fused fp32 tf32 kernel when caps exceeded.

#define BM      32
#define DDIM    256
#define THREADS 512
#define MAX_S   40
#define ASTRIDE 260     // fallback A tile row stride (words)
#define WSTRIDE 264     // fallback W chunk row stride (words)
#define KH      264     // fp16 row stride (halves) for persistent gemm smem
#define NTAB_CAP 200000
#define NODE_CAP 65536
#define GW      16      // nodes (warps) per gather block

// fallback-kernel smem
#define AS_BYTES  (BM * ASTRIDE * 4)
#define WS_BYTES  (2 * 8 * WSTRIDE * 4)
#define IDX_BYTES (BM * MAX_S * 4)
#define R2_BYTES  (WS_BYTES > IDX_BYTES ? WS_BYTES : IDX_BYTES)
#define SMEM_BYTES (AS_BYTES + R2_BYTES + 128)

// persistent-gemm smem
#define WN_BYTES   (DDIM * KH * 2)        // 135168
#define A16_BYTES  (BM * KH * 2)          // 16896
#define OUT_BYTES  (BM * ASTRIDE * 4)     // 33280
#define PG_SMEM    (WN_BYTES + A16_BYTES + OUT_BYTES + 128)

__device__ uint4 g_feat16[(size_t)NTAB_CAP * 32];
__device__ uint4 g_agg16[(size_t)NODE_CAP * 32];
__device__ uint4 g_w16t[DDIM * DDIM / 8];

__device__ __forceinline__ uint32_t f2tf32(float f) {
    uint32_t u;
    asm("cvt.rna.tf32.f32 %0, %1;" : "=r"(u) : "f"(f));
    return u;
}

__device__ __forceinline__ uint32_t smem_u32(const void* p) {
    uint32_t a;
    asm("{ .reg .u64 t; cvta.to.shared.u64 t, %1; cvt.u32.u64 %0, t; }"
        : "=r"(a) : "l"(p));
    return a;
}

__device__ __forceinline__ int ldg_stream(const int* p) {
    int v;
    asm("ld.global.cs.s32 %0, [%1];" : "=r"(v) : "l"(p));
    return v;
}

__device__ __forceinline__ float4 ldg_stream4(const float4* p) {
    float4 v;
    asm("ld.global.cs.v4.f32 {%0,%1,%2,%3}, [%4];"
        : "=f"(v.x), "=f"(v.y), "=f"(v.z), "=f"(v.w) : "l"(p));
    return v;
}

__device__ __forceinline__ uint4 ldg_stream_u4(const uint4* p) {
    uint4 v;
    asm("ld.global.cs.v4.b32 {%0,%1,%2,%3}, [%4];"
        : "=r"(v.x), "=r"(v.y), "=r"(v.z), "=r"(v.w) : "l"(p));
    return v;
}

__device__ __forceinline__ void stg_stream(float4* p, float4 v) {
    asm volatile("st.global.cs.v4.f32 [%0], {%1,%2,%3,%4};"
                 :: "l"(p), "f"(v.x), "f"(v.y), "f"(v.z), "f"(v.w));
}

__device__ __forceinline__ void stg_stream_u4(uint4* p, uint4 v) {
    asm volatile("st.global.cs.v4.b32 [%0], {%1,%2,%3,%4};"
                 :: "l"(p), "r"(v.x), "r"(v.y), "r"(v.z), "r"(v.w));
}

__device__ __forceinline__ void ldsm_x4(uint32_t& r0, uint32_t& r1,
                                        uint32_t& r2, uint32_t& r3,
                                        uint32_t addr)
{
    asm volatile("ldmatrix.sync.aligned.m8n8.x4.shared.b16 {%0,%1,%2,%3}, [%4];"
                 : "=r"(r0), "=r"(r1), "=r"(r2), "=r"(r3) : "r"(addr));
}

__device__ __forceinline__ void mma_tf32(float* d,
                                         uint32_t a0, uint32_t a1,
                                         uint32_t a2, uint32_t a3,
                                         uint32_t b0, uint32_t b1)
{
    asm("mma.sync.aligned.m16n8k8.row.col.f32.tf32.tf32.f32 "
        "{%0,%1,%2,%3}, {%4,%5,%6,%7}, {%8,%9}, {%0,%1,%2,%3};"
        : "+f"(d[0]), "+f"(d[1]), "+f"(d[2]), "+f"(d[3])
        : "r"(a0), "r"(a1), "r"(a2), "r"(a3), "r"(b0), "r"(b1));
}

__device__ __forceinline__ void mma_f16(float* d,
                                        uint32_t a0, uint32_t a1,
                                        uint32_t a2, uint32_t a3,
                                        uint32_t b0, uint32_t b1)
{
    asm("mma.sync.aligned.m16n8k16.row.col.f32.f16.f16.f32 "
        "{%0,%1,%2,%3}, {%4,%5,%6,%7}, {%8,%9}, {%0,%1,%2,%3};"
        : "+f"(d[0]), "+f"(d[1]), "+f"(d[2]), "+f"(d[3])
        : "r"(a0), "r"(a1), "r"(a2), "r"(a3), "r"(b0), "r"(b1));
}

__device__ __forceinline__ void acc_single(float* acc, uint4 x) {
    const __half2* hx = reinterpret_cast<const __half2*>(&x);
    #pragma unroll
    for (int j = 0; j < 4; ++j) {
        float2 f = __half22float2(hx[j]);
        acc[2*j]   += f.x;
        acc[2*j+1] += f.y;
    }
}

// ---- K1: fp32 -> fp16 table conversion ----
__global__ void cvt_f16_kernel(const float4* __restrict__ F4, int n_vec)
{
    int i      = blockIdx.x * blockDim.x + threadIdx.x;
    int stride = gridDim.x * blockDim.x;
    for (; i < n_vec; i += stride) {
        float4 f0 = ldg_stream4(F4 + 2 * (long)i);
        float4 f1 = ldg_stream4(F4 + 2 * (long)i + 1);
        __half2 h0 = __float22half2_rn(make_float2(f0.x, f0.y));
        __half2 h1 = __float22half2_rn(make_float2(f0.z, f0.w));
        __half2 h2 = __float22half2_rn(make_float2(f1.x, f1.y));
        __half2 h3 = __float22half2_rn(make_float2(f1.z, f1.w));
        uint4 u;
        u.x = *reinterpret_cast<uint32_t*>(&h0);
        u.y = *reinterpret_cast<uint32_t*>(&h1);
        u.z = *reinterpret_cast<uint32_t*>(&h2);
        u.w = *reinterpret_cast<uint32_t*>(&h3);
        g_feat16[i] = u;
    }
}

// ---- K1c: W fp32 [k][n] -> fp16 transposed [n][k] ----
__global__ void cvt_w16_kernel(const float* __restrict__ W)
{
    int k = blockIdx.x;
    int n = threadIdx.x;
    float w = W[k * DDIM + n];
    reinterpret_cast<__half*>(g_w16t)[n * DDIM + k] = __float2half_rn(w);
}

// ---- K2a: high-occupancy gather+mean -> fp16 agg scratch (.cs) ----
__global__ __launch_bounds__(THREADS, 3)
void gather_kernel(const int* __restrict__ node_idx,
                   const int* __restrict__ neigh_idx,
                   int n_nodes, int n_samp)
{
    __shared__ int idxS[GW * MAX_S];

    const int tid       = threadIdx.x;
    const int blockBase = blockIdx.x * GW;
    const int rows      = min(GW, n_nodes - blockBase);
    const int S         = n_samp + 1;

    for (int i = tid; i < rows * S; i += THREADS) {
        int n = i / S, s = i - n * S;
        int gn = blockBase + n;
        idxS[n * S + s] = (s == 0) ? ldg_stream(node_idx + gn)
                                   : ldg_stream(neigh_idx + (long)gn * n_samp + (s - 1));
    }
    __syncthreads();

    const int lane = tid & 31;
    const int w    = tid >> 5;
    if (w >= rows) return;
    const int* ip = idxS + w * S;

    float acc[8];
    #pragma unroll
    for (int j = 0; j < 8; ++j) acc[j] = 0.0f;

    int s = 0;
    #pragma unroll 1
    for (; s + 4 <= S; s += 4) {
        uint4 u0 = g_feat16[(long)ip[s + 0] * 32 + lane];
        uint4 u1 = g_feat16[(long)ip[s + 1] * 32 + lane];
        uint4 u2 = g_feat16[(long)ip[s + 2] * 32 + lane];
        uint4 u3 = g_feat16[(long)ip[s + 3] * 32 + lane];
        acc_single(acc, u0);
        acc_single(acc, u1);
        acc_single(acc, u2);
        acc_single(acc, u3);
    }
    for (; s < S; ++s) {
        uint4 u = g_feat16[(long)ip[s] * 32 + lane];
        acc_single(acc, u);
    }

    const float invS = 1.0f / (float)S;
    __half2 p0 = __floats2half2_rn(acc[0] * invS, acc[1] * invS);
    __half2 p1 = __floats2half2_rn(acc[2] * invS, acc[3] * invS);
    __half2 p2 = __floats2half2_rn(acc[4] * invS, acc[5] * invS);
    __half2 p3 = __floats2half2_rn(acc[6] * invS, acc[7] * invS);
    uint4 o;
    o.x = *reinterpret_cast<uint32_t*>(&p0);
    o.y = *reinterpret_cast<uint32_t*>(&p1);
    o.z = *reinterpret_cast<uint32_t*>(&p2);
    o.w = *reinterpret_cast<uint32_t*>(&p3);
    stg_stream_u4(g_agg16 + (size_t)(blockBase + w) * 32 + lane, o);
}

// ---- K2b: persistent fp16 GEMM + epilogue (ldmatrix fragment loads) ----
__global__ __launch_bounds__(THREADS, 1)
void gemm_kernel(const float* __restrict__ b,
                 float*       __restrict__ out,
                 int n_nodes, int ntiles)
{
    extern __shared__ char smem[];
    __half* Wn  = reinterpret_cast<__half*>(smem);                 // [256][KH]
    __half* A16 = reinterpret_cast<__half*>(smem + WN_BYTES);      // [32][KH]
    float*  OUT = reinterpret_cast<float*>(smem + WN_BYTES + A16_BYTES); // [32][260]
    float*  invN = reinterpret_cast<float*>(smem + WN_BYTES + A16_BYTES + OUT_BYTES);

    const int tid  = threadIdx.x;
    const int lane = tid & 31, warp = tid >> 5;
    const int g    = lane >> 2, t = lane & 3;
    const int mrow  = (warp & 1) * 16;
    const int nbase = (warp >> 1) * 32;

    // ---- stage full W (fp16, n-major) once ----
    for (int i = tid; i < DDIM * 32; i += THREADS) {
        int n = i >> 5, c = i & 31;
        *reinterpret_cast<uint4*>(Wn + n * KH + c * 8) = g_w16t[i];
    }

    // ---- per-lane ldmatrix base addresses ----
    // A x4: matrices (m-lo,k-lo),(m-hi,k-lo),(m-lo,k-hi),(m-hi,k-hi)
    //   lane -> row = mrow + ((lane>>3)&1)*8 + (lane&7); kcol = (lane>>4)*8
    const int a_row = mrow + ((lane >> 3) & 1) * 8 + (lane & 7);
    const int a_kc  = (lane >> 4) * 8;
    const uint32_t a_base = smem_u32(A16) + (uint32_t)(a_row * KH + a_kc) * 2;

    // B x4 (pair p covers j=2p,2p+1): matrices (j,k-lo),(j,k-hi),(j+1,k-lo),(j+1,k-hi)
    //   lane -> row = nbase + 16p + ((lane>>4)&1)*8 + (lane&7); kcol = ((lane>>3)&1)*8
    const int b_rowoff = ((lane >> 4) & 1) * 8 + (lane & 7);
    const int b_kc     = ((lane >> 3) & 1) * 8;
    uint32_t b_base[2];
    #pragma unroll
    for (int p = 0; p < 2; ++p)
        b_base[p] = smem_u32(Wn) +
                    (uint32_t)((nbase + 16 * p + b_rowoff) * KH + b_kc) * 2;

    // hoist bias
    float2 bb[4];
    #pragma unroll
    for (int j = 0; j < 4; ++j)
        bb[j] = __ldg(reinterpret_cast<const float2*>(b + nbase + 8 * j + 2 * t));

    float4* out4 = reinterpret_cast<float4*>(out);

    for (int tile = blockIdx.x; tile < ntiles; tile += gridDim.x) {
        const int blockBase = tile * BM;
        const int rows      = min(BM, n_nodes - blockBase);

        // ---- load fp16 A tile (raw copy) ----
        __syncthreads();   // previous tile fully consumed
        const uint4* A4 = g_agg16 + (size_t)blockBase * 32;
        for (int i = tid; i < BM * 32; i += THREADS) {
            int r = i >> 5, c = i & 31;
            *reinterpret_cast<uint4*>(A16 + r * KH + c * 8) = ldg_stream_u4(A4 + i);
        }
        __syncthreads();

        // ---- mainloop: 16 k-steps, 3 LDSM.x4 + 4 MMA each ----
        float d[4][4];
        #pragma unroll
        for (int j = 0; j < 4; ++j)
            #pragma unroll
            for (int c = 0; c < 4; ++c) d[j][c] = 0.0f;

        #pragma unroll 4
        for (int k0 = 0; k0 < DDIM; k0 += 16) {
            uint32_t fa0, fa1, fa2, fa3;
            ldsm_x4(fa0, fa1, fa2, fa3, a_base + 2 * k0);

            uint32_t b00, b01, b10, b11;
            ldsm_x4(b00, b01, b10, b11, b_base[0] + 2 * k0);
            uint32_t b20, b21, b30, b31;
            ldsm_x4(b20, b21, b30, b31, b_base[1] + 2 * k0);

            mma_f16(d[0], fa0, fa1, fa2, fa3, b00, b01);
            mma_f16(d[1], fa0, fa1, fa2, fa3, b10, b11);
            mma_f16(d[2], fa0, fa1, fa2, fa3, b20, b21);
            mma_f16(d[3], fa0, fa1, fa2, fa3, b30, b31);
        }

        // ---- epilogue: bias + relu into OUT ----
        #pragma unroll
        for (int j = 0; j < 4; ++j) {
            int col = nbase + 8 * j + 2 * t;
            float2 lo, hi;
            lo.x = fmaxf(d[j][0] + bb[j].x, 0.0f);
            lo.y = fmaxf(d[j][1] + bb[j].y, 0.0f);
            hi.x = fmaxf(d[j][2] + bb[j].x, 0.0f);
            hi.y = fmaxf(d[j][3] + bb[j].y, 0.0f);
            *reinterpret_cast<float2*>(&OUT[(mrow + g)     * ASTRIDE + col]) = lo;
            *reinterpret_cast<float2*>(&OUT[(mrow + g + 8) * ASTRIDE + col]) = hi;
        }
        __syncthreads();

        // ---- per-row L2 norm: warp w handles rows 2w, 2w+1 ----
        #pragma unroll
        for (int rr = 0; rr < 2; ++rr) {
            int row = warp * 2 + rr;
            float s = 0.0f;
            #pragma unroll
            for (int jj = 0; jj < 8; ++jj) {
                float v = OUT[row * ASTRIDE + lane + 32 * jj];
                s = fmaf(v, v, s);
            }
            #pragma unroll
            for (int o = 16; o > 0; o >>= 1)
                s += __shfl_xor_sync(0xffffffffu, s, o);
            if (lane == 0)
                invN[row] = 1.0f / fmaxf(sqrtf(s), 1e-12f);
        }
        __syncthreads();

        // ---- normalized streaming store ----
        for (int i = tid; i < BM * (DDIM / 4); i += THREADS) {
            int r = i >> 6, c = i & 63;
            if (r < rows) {
                float4 v = *reinterpret_cast<const float4*>(&OUT[r * ASTRIDE + 4 * c]);
                float sc = invN[r];
                v.x *= sc; v.y *= sc; v.z *= sc; v.w *= sc;
                stg_stream(out4 + (long)(blockBase + r) * (DDIM / 4) + c, v);
            }
        }
    }
}

// ---- Fallback: fused fp32/tf32 kernel (caps exceeded) ----
__global__ __launch_bounds__(THREADS, 2)
void gsage_fused_f32(const int*   __restrict__ node_idx,
                     const int*   __restrict__ neigh_idx,
                     const float* __restrict__ features,
                     const float* __restrict__ W,
                     const float* __restrict__ b,
                     float*       __restrict__ out,
                     int n_nodes, int n_samp)
{
    extern __shared__ char smem[];
    float*    As   = reinterpret_cast<float*>(smem);
    int*      idxS = reinterpret_cast<int*>(smem + AS_BYTES);
    uint32_t* Ws   = reinterpret_cast<uint32_t*>(smem + AS_BYTES);
    float*    invN = reinterpret_cast<float*>(smem + AS_BYTES + R2_BYTES);

    const int tid       = threadIdx.x;
    const int blockBase = blockIdx.x * BM;
    const int rows      = min(BM, n_nodes - blockBase);
    const int S         = n_samp + 1;

    for (int i = tid; i < rows * S; i += THREADS) {
        int n = i / S, s = i - n * S;
        int gn = blockBase + n;
        idxS[n * S + s] = (s == 0) ? ldg_stream(node_idx + gn)
                                   : ldg_stream(neigh_idx + (long)gn * n_samp + (s - 1));
    }
    __syncthreads();

    const float invS = 1.0f / (float)S;
    {
        const int c4 = tid & 63;
        const int n0 = (tid >> 6) * 4;
        const float4* F4 = reinterpret_cast<const float4*>(features);

        const bool v0 = (n0 + 0) < rows, v1 = (n0 + 1) < rows;
        const bool v2 = (n0 + 2) < rows, v3 = (n0 + 3) < rows;
        const int* ip0 = idxS + (v0 ? (n0 + 0) * S : 0);
        const int* ip1 = idxS + (v1 ? (n0 + 1) * S : 0);
        const int* ip2 = idxS + (v2 ? (n0 + 2) * S : 0);
        const int* ip3 = idxS + (v3 ? (n0 + 3) * S : 0);

        float4 a0 = {0,0,0,0}, a1 = {0,0,0,0}, a2 = {0,0,0,0}, a3 = {0,0,0,0};
        #pragma unroll 4
        for (int s = 0; s < S; ++s) {
            float4 t0 = __ldg(F4 + (long)ip0[s] * (DDIM/4) + c4);
            float4 t1 = __ldg(F4 + (long)ip1[s] * (DDIM/4) + c4);
            float4 t2 = __ldg(F4 + (long)ip2[s] * (DDIM/4) + c4);
            float4 t3 = __ldg(F4 + (long)ip3[s] * (DDIM/4) + c4);
            a0.x += t0.x; a0.y += t0.y; a0.z += t0.z; a0.w += t0.w;
            a1.x += t1.x; a1.y += t1.y; a1.z += t1.z; a1.w += t1.w;
            a2.x += t2.x; a2.y += t2.y; a2.z += t2.z; a2.w += t2.w;
            a3.x += t3.x; a3.y += t3.y; a3.z += t3.z; a3.w += t3.w;
        }
        const float m0 = v0 ? invS : 0.0f, m1 = v1 ? invS : 0.0f;
        const float m2 = v2 ? invS : 0.0f, m3 = v3 ? invS : 0.0f;
        uint4 u0 = { f2tf32(a0.x*m0), f2tf32(a0.y*m0), f2tf32(a0.z*m0), f2tf32(a0.w*m0) };
        uint4 u1 = { f2tf32(a1.x*m1), f2tf32(a1.y*m1), f2tf32(a1.z*m1), f2tf32(a1.w*m1) };
        uint4 u2 = { f2tf32(a2.x*m2), f2tf32(a2.y*m2), f2tf32(a2.z*m2), f2tf32(a2.w*m2) };
        uint4 u3 = { f2tf32(a3.x*m3), f2tf32(a3.y*m3), f2tf32(a3.z*m3), f2tf32(a3.w*m3) };
        *reinterpret_cast<uint4*>(&As[(n0 + 0) * ASTRIDE + 4 * c4]) = u0;
        *reinterpret_cast<uint4*>(&As[(n0 + 1) * ASTRIDE + 4 * c4]) = u1;
        *reinterpret_cast<uint4*>(&As[(n0 + 2) * ASTRIDE + 4 * c4]) = u2;
        *reinterpret_cast<uint4*>(&As[(n0 + 3) * ASTRIDE + 4 * c4]) = u3;
    }
    __syncthreads();

    const int lane = tid & 31, warp = tid >> 5;
    const int g    = lane >> 2, t = lane & 3;
    const int mrow  = (warp & 1) * 16;
    const int nbase = (warp >> 1) * 32;
    const int kk = tid >> 6;
    const int n4 = (tid & 63) * 4;

    float d[4][4];
    #pragma unroll
    for (int j = 0; j < 4; ++j)
        #pragma unroll
        for (int c = 0; c < 4; ++c) d[j][c] = 0.0f;

    const uint32_t* a_lo = reinterpret_cast<const uint32_t*>(As) + (mrow + g) * ASTRIDE;
    const uint32_t* a_hi = a_lo + 8 * ASTRIDE;

    {
        float4 w = *reinterpret_cast<const float4*>(&W[kk * DDIM + n4]);
        uint4 u = { f2tf32(w.x), f2tf32(w.y), f2tf32(w.z), f2tf32(w.w) };
        *reinterpret_cast<uint4*>(&Ws[kk * WSTRIDE + n4]) = u;
    }
    __syncthreads();

    for (int kc = 0; kc < DDIM / 8; ++kc) {
        const uint32_t* Wb = Ws + (kc & 1) * (8 * WSTRIDE);
        if (kc + 1 < DDIM / 8) {
            float4 w = *reinterpret_cast<const float4*>(
                           &W[((kc + 1) * 8 + kk) * DDIM + n4]);
            uint4 u = { f2tf32(w.x), f2tf32(w.y), f2tf32(w.z), f2tf32(w.w) };
            *reinterpret_cast<uint4*>(
                &Ws[((kc + 1) & 1) * (8 * WSTRIDE) + kk * WSTRIDE + n4]) = u;
        }
        const int k0 = kc * 8;
        uint32_t fa0 = a_lo[k0 + t];
        uint32_t fa1 = a_hi[k0 + t];
        uint32_t fa2 = a_lo[k0 + t + 4];
        uint32_t fa3 = a_hi[k0 + t + 4];
        #pragma unroll
        for (int j = 0; j < 4; ++j) {
            int n = nbase + 8 * j + g;
            uint32_t b0 = Wb[t * WSTRIDE + n];
            uint32_t b1 = Wb[(t + 4) * WSTRIDE + n];
            mma_tf32(d[j], fa0, fa1, fa2, fa3, b0, b1);
        }
        __syncthreads();
    }

    #pragma unroll
    for (int j = 0; j < 4; ++j) {
        int col = nbase + 8 * j + 2 * t;
        float2 bbf = __ldg(reinterpret_cast<const float2*>(b + col));
        float2 lo, hi;
        lo.x = fmaxf(d[j][0] + bbf.x, 0.0f);
        lo.y = fmaxf(d[j][1] + bbf.y, 0.0f);
        hi.x = fmaxf(d[j][2] + bbf.x, 0.0f);
        hi.y = fmaxf(d[j][3] + bbf.y, 0.0f);
        *reinterpret_cast<float2*>(&As[(mrow + g)     * ASTRIDE + col]) = lo;
        *reinterpret_cast<float2*>(&As[(mrow + g + 8) * ASTRIDE + col]) = hi;
    }
    __syncthreads();

    #pragma unroll
    for (int rr = 0; rr < 2; ++rr) {
        int row = warp * 2 + rr;
        float s = 0.0f;
        #pragma unroll
        for (int jj = 0; jj < 8; ++jj) {
            float v = As[row * ASTRIDE + lane + 32 * jj];
            s = fmaf(v, v, s);
        }
        #pragma unroll
        for (int o = 16; o > 0; o >>= 1)
            s += __shfl_xor_sync(0xffffffffu, s, o);
        if (lane == 0)
            invN[row] = 1.0f / fmaxf(sqrtf(s), 1e-12f);
    }
    __syncthreads();

    float4* out4 = reinterpret_cast<float4*>(out);
    for (int i = tid; i < BM * (DDIM / 4); i += THREADS) {
        int r = i >> 6, c = i & 63;
        if (r < rows) {
            float4 v = *reinterpret_cast<const float4*>(&As[r * ASTRIDE + 4 * c]);
            float sc = invN[r];
            v.x *= sc; v.y *= sc; v.z *= sc; v.w *= sc;
            stg_stream(out4 + (long)(blockBase + r) * (DDIM / 4) + c, v);
        }
    }
}

extern "C" void kernel_launch(void* const* d_in, const int* in_sizes, int n_in,
                              void* d_out, int out_size)
{
    const int*   node_idx  = (const int*)  d_in[0];
    const int*   neigh_idx = (const int*)  d_in[1];
    const float* features  = (const float*)d_in[2];
    const float* W         = (const float*)d_in[3];
    const float* b         = (const float*)d_in[4];
    float*       out       = (float*)      d_out;

    const int n_nodes = in_sizes[0];
    const int n_samp  = in_sizes[1] / n_nodes;   // 32
    const int n_table = in_sizes[2] / DDIM;
    const int ntiles  = (n_nodes + BM - 1) / BM;

    if (n_table <= NTAB_CAP && n_nodes <= NODE_CAP && n_samp + 1 <= MAX_S) {
        const int n_vec = n_table * 32;
        cvt_f16_kernel<<<3125, 512>>>(
            reinterpret_cast<const float4*>(features), n_vec);
        cvt_w16_kernel<<<DDIM, DDIM>>>(W);

        const int ggrid = (n_nodes + GW - 1) / GW;
        gather_kernel<<<ggrid, THREADS>>>(node_idx, neigh_idx, n_nodes, n_samp);

        cudaFuncSetAttribute(gemm_kernel,
                             cudaFuncAttributeMaxDynamicSharedMemorySize, PG_SMEM);
        const int mgrid = (ntiles < 148) ? ntiles : 148;
        gemm_kernel<<<mgrid, THREADS, PG_SMEM>>>(b, out, n_nodes, ntiles);
    } else {
        cudaFuncSetAttribute(gsage_fused_f32,
                             cudaFuncAttributeMaxDynamicSharedMemorySize, SMEM_BYTES);
        const int grid = (n_nodes + BM - 1) / BM;
        gsage_fused_f32<<<grid, THREADS, SMEM_BYTES>>>(
            node_idx, neigh_idx, features, W, b, out, n_nodes, n_samp);
    }
}

// round 17
// speedup vs baseline: 1.5444x; 1.0684x over previous
#include <cuda_runtime.h>
#include <cuda_bf16.h>
#include <cuda_fp16.h>
#include <cstdint>

// Fused GraphSAGE layer, split pipeline (one graph):
//  K1 : feature table fp32 -> fp16 scratch (102MB; L2-hot)
//  K1c: W fp32 -> fp16 TRANSPOSED scratch (128KB, n-major)
//  K2a: gather+mean at high occupancy -> fp16 agg scratch (.cs)
//  K2b: PERSISTENT fp16 m16n8k16 GEMM, 1024 threads, 2 tiles/iter
//       (32 warps/SM), whole W in smem, ldmatrix loads, register epilogue
//       (no OUT smem): bias/relu, quad-shuffle + smem-stripe row L2 norm,
//       direct streaming store.
// Fallback: fused fp32 tf32 kernel when caps exceeded.
// NOTE: tcgen05 is NOT available (harness PTX targets compute_103).

#define BM      32
#define DDIM    256
#define THREADS 512
#define GT      1024    // gemm threads
#define MAX_S   40
#define ASTRIDE 260
#define WSTRIDE 264
#define KH      264     // fp16 row stride (halves)
#define NTAB_CAP 200000
#define NODE_CAP 65536
#define GW      16

// fallback-kernel smem
#define AS_BYTES  (BM * ASTRIDE * 4)
#define WS_BYTES  (2 * 8 * WSTRIDE * 4)
#define IDX_BYTES (BM * MAX_S * 4)
#define R2_BYTES  (WS_BYTES > IDX_BYTES ? WS_BYTES : IDX_BYTES)
#define SMEM_BYTES (AS_BYTES + R2_BYTES + 128)

// persistent-gemm smem
#define WN_BYTES   (DDIM * KH * 2)        // 135168
#define A16_BYTES  (2 * BM * KH * 2)      // 33792 (two tiles)
#define NORM_BYTES (2 * BM * 8 * 4)       // 2048
#define PG_SMEM    (WN_BYTES + A16_BYTES + NORM_BYTES + 128)

__device__ uint4 g_feat16[(size_t)NTAB_CAP * 32];
__device__ uint4 g_agg16[(size_t)NODE_CAP * 32];
__device__ uint4 g_w16t[DDIM * DDIM / 8];

__device__ __forceinline__ uint32_t f2tf32(float f) {
    uint32_t u;
    asm("cvt.rna.tf32.f32 %0, %1;" : "=r"(u) : "f"(f));
    return u;
}

__device__ __forceinline__ uint32_t smem_u32(const void* p) {
    uint32_t a;
    asm("{ .reg .u64 t; cvta.to.shared.u64 t, %1; cvt.u32.u64 %0, t; }"
        : "=r"(a) : "l"(p));
    return a;
}

__device__ __forceinline__ int ldg_stream(const int* p) {
    int v;
    asm("ld.global.cs.s32 %0, [%1];" : "=r"(v) : "l"(p));
    return v;
}

__device__ __forceinline__ float4 ldg_stream4(const float4* p) {
    float4 v;
    asm("ld.global.cs.v4.f32 {%0,%1,%2,%3}, [%4];"
        : "=f"(v.x), "=f"(v.y), "=f"(v.z), "=f"(v.w) : "l"(p));
    return v;
}

__device__ __forceinline__ uint4 ldg_stream_u4(const uint4* p) {
    uint4 v;
    asm("ld.global.cs.v4.b32 {%0,%1,%2,%3}, [%4];"
        : "=r"(v.x), "=r"(v.y), "=r"(v.z), "=r"(v.w) : "l"(p));
    return v;
}

__device__ __forceinline__ void stg_stream(float4* p, float4 v) {
    asm volatile("st.global.cs.v4.f32 [%0], {%1,%2,%3,%4};"
                 :: "l"(p), "f"(v.x), "f"(v.y), "f"(v.z), "f"(v.w));
}

__device__ __forceinline__ void stg_stream2(float2* p, float2 v) {
    asm volatile("st.global.cs.v2.f32 [%0], {%1,%2};"
                 :: "l"(p), "f"(v.x), "f"(v.y));
}

__device__ __forceinline__ void stg_stream_u4(uint4* p, uint4 v) {
    asm volatile("st.global.cs.v4.b32 [%0], {%1,%2,%3,%4};"
                 :: "l"(p), "r"(v.x), "r"(v.y), "r"(v.z), "r"(v.w));
}

__device__ __forceinline__ void ldsm_x4(uint32_t& r0, uint32_t& r1,
                                        uint32_t& r2, uint32_t& r3,
                                        uint32_t addr)
{
    asm volatile("ldmatrix.sync.aligned.m8n8.x4.shared.b16 {%0,%1,%2,%3}, [%4];"
                 : "=r"(r0), "=r"(r1), "=r"(r2), "=r"(r3) : "r"(addr));
}

__device__ __forceinline__ void mma_tf32(float* d,
                                         uint32_t a0, uint32_t a1,
                                         uint32_t a2, uint32_t a3,
                                         uint32_t b0, uint32_t b1)
{
    asm("mma.sync.aligned.m16n8k8.row.col.f32.tf32.tf32.f32 "
        "{%0,%1,%2,%3}, {%4,%5,%6,%7}, {%8,%9}, {%0,%1,%2,%3};"
        : "+f"(d[0]), "+f"(d[1]), "+f"(d[2]), "+f"(d[3])
        : "r"(a0), "r"(a1), "r"(a2), "r"(a3), "r"(b0), "r"(b1));
}

__device__ __forceinline__ void mma_f16(float* d,
                                        uint32_t a0, uint32_t a1,
                                        uint32_t a2, uint32_t a3,
                                        uint32_t b0, uint32_t b1)
{
    asm("mma.sync.aligned.m16n8k16.row.col.f32.f16.f16.f32 "
        "{%0,%1,%2,%3}, {%4,%5,%6,%7}, {%8,%9}, {%0,%1,%2,%3};"
        : "+f"(d[0]), "+f"(d[1]), "+f"(d[2]), "+f"(d[3])
        : "r"(a0), "r"(a1), "r"(a2), "r"(a3), "r"(b0), "r"(b1));
}

__device__ __forceinline__ void acc_single(float* acc, uint4 x) {
    const __half2* hx = reinterpret_cast<const __half2*>(&x);
    #pragma unroll
    for (int j = 0; j < 4; ++j) {
        float2 f = __half22float2(hx[j]);
        acc[2*j]   += f.x;
        acc[2*j+1] += f.y;
    }
}

// ---- K1: fp32 -> fp16 table conversion ----
__global__ void cvt_f16_kernel(const float4* __restrict__ F4, int n_vec)
{
    int i      = blockIdx.x * blockDim.x + threadIdx.x;
    int stride = gridDim.x * blockDim.x;
    for (; i < n_vec; i += stride) {
        float4 f0 = ldg_stream4(F4 + 2 * (long)i);
        float4 f1 = ldg_stream4(F4 + 2 * (long)i + 1);
        __half2 h0 = __float22half2_rn(make_float2(f0.x, f0.y));
        __half2 h1 = __float22half2_rn(make_float2(f0.z, f0.w));
        __half2 h2 = __float22half2_rn(make_float2(f1.x, f1.y));
        __half2 h3 = __float22half2_rn(make_float2(f1.z, f1.w));
        uint4 u;
        u.x = *reinterpret_cast<uint32_t*>(&h0);
        u.y = *reinterpret_cast<uint32_t*>(&h1);
        u.z = *reinterpret_cast<uint32_t*>(&h2);
        u.w = *reinterpret_cast<uint32_t*>(&h3);
        g_feat16[i] = u;
    }
}

// ---- K1c: W fp32 [k][n] -> fp16 transposed [n][k] ----
__global__ void cvt_w16_kernel(const float* __restrict__ W)
{
    int k = blockIdx.x;
    int n = threadIdx.x;
    float w = W[k * DDIM + n];
    reinterpret_cast<__half*>(g_w16t)[n * DDIM + k] = __float2half_rn(w);
}

// ---- K2a: high-occupancy gather+mean -> fp16 agg scratch (.cs) ----
__global__ __launch_bounds__(THREADS, 3)
void gather_kernel(const int* __restrict__ node_idx,
                   const int* __restrict__ neigh_idx,
                   int n_nodes, int n_samp)
{
    __shared__ int idxS[GW * MAX_S];

    const int tid       = threadIdx.x;
    const int blockBase = blockIdx.x * GW;
    const int rows      = min(GW, n_nodes - blockBase);
    const int S         = n_samp + 1;

    for (int i = tid; i < rows * S; i += THREADS) {
        int n = i / S, s = i - n * S;
        int gn = blockBase + n;
        idxS[n * S + s] = (s == 0) ? ldg_stream(node_idx + gn)
                                   : ldg_stream(neigh_idx + (long)gn * n_samp + (s - 1));
    }
    __syncthreads();

    const int lane = tid & 31;
    const int w    = tid >> 5;
    if (w >= rows) return;
    const int* ip = idxS + w * S;

    float acc[8];
    #pragma unroll
    for (int j = 0; j < 8; ++j) acc[j] = 0.0f;

    int s = 0;
    #pragma unroll 1
    for (; s + 4 <= S; s += 4) {
        uint4 u0 = g_feat16[(long)ip[s + 0] * 32 + lane];
        uint4 u1 = g_feat16[(long)ip[s + 1] * 32 + lane];
        uint4 u2 = g_feat16[(long)ip[s + 2] * 32 + lane];
        uint4 u3 = g_feat16[(long)ip[s + 3] * 32 + lane];
        acc_single(acc, u0);
        acc_single(acc, u1);
        acc_single(acc, u2);
        acc_single(acc, u3);
    }
    for (; s < S; ++s) {
        uint4 u = g_feat16[(long)ip[s] * 32 + lane];
        acc_single(acc, u);
    }

    const float invS = 1.0f / (float)S;
    __half2 p0 = __floats2half2_rn(acc[0] * invS, acc[1] * invS);
    __half2 p1 = __floats2half2_rn(acc[2] * invS, acc[3] * invS);
    __half2 p2 = __floats2half2_rn(acc[4] * invS, acc[5] * invS);
    __half2 p3 = __floats2half2_rn(acc[6] * invS, acc[7] * invS);
    uint4 o;
    o.x = *reinterpret_cast<uint32_t*>(&p0);
    o.y = *reinterpret_cast<uint32_t*>(&p1);
    o.z = *reinterpret_cast<uint32_t*>(&p2);
    o.w = *reinterpret_cast<uint32_t*>(&p3);
    stg_stream_u4(g_agg16 + (size_t)(blockBase + w) * 32 + lane, o);
}

// ---- K2b: persistent fp16 GEMM, 2 tiles/iter, register epilogue ----
__global__ __launch_bounds__(GT, 1)
void gemm_kernel(const float* __restrict__ b,
                 float*       __restrict__ out,
                 int n_nodes, int ntiles)
{
    extern __shared__ char smem[];
    __half* Wn   = reinterpret_cast<__half*>(smem);                     // [256][KH]
    __half* A16  = reinterpret_cast<__half*>(smem + WN_BYTES);          // [2][32][KH]
    float*  normP = reinterpret_cast<float*>(smem + WN_BYTES + A16_BYTES); // [2][32][8]

    const int tid  = threadIdx.x;
    const int lane = tid & 31, wid = tid >> 5;
    const int tsel  = wid >> 4;            // which tile (0/1)
    const int wslot = wid & 15;
    const int g     = lane >> 2, t = lane & 3;
    const int mrow   = (wslot & 1) * 16;
    const int nbase  = (wslot >> 1) * 32;
    const int stripe = wslot >> 1;         // 0..7

    // ---- stage full W once ----
    for (int i = tid; i < DDIM * 32; i += GT) {
        int n = i >> 5, c = i & 31;
        *reinterpret_cast<uint4*>(Wn + n * KH + c * 8) = g_w16t[i];
    }

    // ---- ldmatrix base addresses ----
    const int a_row = mrow + ((lane >> 3) & 1) * 8 + (lane & 7);
    const int a_kc  = (lane >> 4) * 8;
    const uint32_t a_base = smem_u32(A16) +
        (uint32_t)((tsel * BM + a_row) * KH + a_kc) * 2;

    const int b_rowoff = ((lane >> 4) & 1) * 8 + (lane & 7);
    const int b_kc     = ((lane >> 3) & 1) * 8;
    uint32_t b_base[2];
    #pragma unroll
    for (int p = 0; p < 2; ++p)
        b_base[p] = smem_u32(Wn) +
                    (uint32_t)((nbase + 16 * p + b_rowoff) * KH + b_kc) * 2;

    // hoist bias (each thread's 8 columns: nbase+8j+2t, +1)
    float2 bb[4];
    #pragma unroll
    for (int j = 0; j < 4; ++j)
        bb[j] = __ldg(reinterpret_cast<const float2*>(b + nbase + 8 * j + 2 * t));

    const int npairs = (ntiles + 1) >> 1;

    for (int pair = blockIdx.x; pair < npairs; pair += gridDim.x) {
        const int tile      = 2 * pair + tsel;
        const int blockBase = tile * BM;               // may exceed n_nodes for tail
        // ---- load both fp16 A tiles (raw copy; in-bounds of scratch) ----
        __syncthreads();   // previous iteration fully consumed
        {
            const uint4* A4 = g_agg16 + (size_t)(2 * pair) * BM * 32;
            int limit = (2 * pair + 2 <= ntiles) ? 2 * BM * 32
                         : (ntiles - 2 * pair) * BM * 32;
            for (int i = tid; i < limit; i += GT) {
                int r = i >> 5, c = i & 31;
                *reinterpret_cast<uint4*>(A16 + r * KH + c * 8) =
                    ldg_stream_u4(A4 + i);
            }
        }
        __syncthreads();

        // ---- mainloop ----
        float d[4][4];
        #pragma unroll
        for (int j = 0; j < 4; ++j)
            #pragma unroll
            for (int c = 0; c < 4; ++c) d[j][c] = 0.0f;

        #pragma unroll 4
        for (int k0 = 0; k0 < DDIM; k0 += 16) {
            uint32_t fa0, fa1, fa2, fa3;
            ldsm_x4(fa0, fa1, fa2, fa3, a_base + 2 * k0);
            uint32_t b00, b01, b10, b11;
            ldsm_x4(b00, b01, b10, b11, b_base[0] + 2 * k0);
            uint32_t b20, b21, b30, b31;
            ldsm_x4(b20, b21, b30, b31, b_base[1] + 2 * k0);

            mma_f16(d[0], fa0, fa1, fa2, fa3, b00, b01);
            mma_f16(d[1], fa0, fa1, fa2, fa3, b10, b11);
            mma_f16(d[2], fa0, fa1, fa2, fa3, b20, b21);
            mma_f16(d[3], fa0, fa1, fa2, fa3, b30, b31);
        }

        // ---- register epilogue: bias+relu, partial row sumsq ----
        float s0 = 0.0f, s1 = 0.0f;   // rows mrow+g, mrow+g+8
        #pragma unroll
        for (int j = 0; j < 4; ++j) {
            d[j][0] = fmaxf(d[j][0] + bb[j].x, 0.0f);
            d[j][1] = fmaxf(d[j][1] + bb[j].y, 0.0f);
            d[j][2] = fmaxf(d[j][2] + bb[j].x, 0.0f);
            d[j][3] = fmaxf(d[j][3] + bb[j].y, 0.0f);
            s0 = fmaf(d[j][0], d[j][0], s0);
            s0 = fmaf(d[j][1], d[j][1], s0);
            s1 = fmaf(d[j][2], d[j][2], s1);
            s1 = fmaf(d[j][3], d[j][3], s1);
        }
        // reduce across the quad (lanes t=0..3 share rows)
        #pragma unroll
        for (int o = 1; o < 4; o <<= 1) {
            s0 += __shfl_xor_sync(0xffffffffu, s0, o);
            s1 += __shfl_xor_sync(0xffffffffu, s1, o);
        }
        if (t == 0) {
            normP[(tsel * BM + mrow + g)     * 8 + stripe] = s0;
            normP[(tsel * BM + mrow + g + 8) * 8 + stripe] = s1;
        }
        __syncthreads();

        // ---- finish norm + store ----
        {
            const float* n0p = &normP[(tsel * BM + mrow + g) * 8];
            const float* n1p = n0p + 8 * 8;
            float tot0 = 0.0f, tot1 = 0.0f;
            #pragma unroll
            for (int jj = 0; jj < 8; ++jj) { tot0 += n0p[jj]; tot1 += n1p[jj]; }
            float inv0 = 1.0f / fmaxf(sqrtf(tot0), 1e-12f);
            float inv1 = 1.0f / fmaxf(sqrtf(tot1), 1e-12f);

            int grow0 = blockBase + mrow + g;
            int grow1 = grow0 + 8;
            if (grow0 < n_nodes) {
                float2* o0 = reinterpret_cast<float2*>(out) +
                             (long)grow0 * (DDIM / 2) + (nbase >> 1) + t;
                #pragma unroll
                for (int j = 0; j < 4; ++j) {
                    float2 v = { d[j][0] * inv0, d[j][1] * inv0 };
                    stg_stream2(o0 + 4 * j, v);
                }
            }
            if (grow1 < n_nodes) {
                float2* o1 = reinterpret_cast<float2*>(out) +
                             (long)grow1 * (DDIM / 2) + (nbase >> 1) + t;
                #pragma unroll
                for (int j = 0; j < 4; ++j) {
                    float2 v = { d[j][2] * inv1, d[j][3] * inv1 };
                    stg_stream2(o1 + 4 * j, v);
                }
            }
        }
    }
}

// ---- Fallback: fused fp32/tf32 kernel (caps exceeded) ----
__global__ __launch_bounds__(THREADS, 2)
void gsage_fused_f32(const int*   __restrict__ node_idx,
                     const int*   __restrict__ neigh_idx,
                     const float* __restrict__ features,
                     const float* __restrict__ W,
                     const float* __restrict__ b,
                     float*       __restrict__ out,
                     int n_nodes, int n_samp)
{
    extern __shared__ char smem[];
    float*    As   = reinterpret_cast<float*>(smem);
    int*      idxS = reinterpret_cast<int*>(smem + AS_BYTES);
    uint32_t* Ws   = reinterpret_cast<uint32_t*>(smem + AS_BYTES);
    float*    invN = reinterpret_cast<float*>(smem + AS_BYTES + R2_BYTES);

    const int tid       = threadIdx.x;
    const int blockBase = blockIdx.x * BM;
    const int rows      = min(BM, n_nodes - blockBase);
    const int S         = n_samp + 1;

    for (int i = tid; i < rows * S; i += THREADS) {
        int n = i / S, s = i - n * S;
        int gn = blockBase + n;
        idxS[n * S + s] = (s == 0) ? ldg_stream(node_idx + gn)
                                   : ldg_stream(neigh_idx + (long)gn * n_samp + (s - 1));
    }
    __syncthreads();

    const float invS = 1.0f / (float)S;
    {
        const int c4 = tid & 63;
        const int n0 = (tid >> 6) * 4;
        const float4* F4 = reinterpret_cast<const float4*>(features);

        const bool v0 = (n0 + 0) < rows, v1 = (n0 + 1) < rows;
        const bool v2 = (n0 + 2) < rows, v3 = (n0 + 3) < rows;
        const int* ip0 = idxS + (v0 ? (n0 + 0) * S : 0);
        const int* ip1 = idxS + (v1 ? (n0 + 1) * S : 0);
        const int* ip2 = idxS + (v2 ? (n0 + 2) * S : 0);
        const int* ip3 = idxS + (v3 ? (n0 + 3) * S : 0);

        float4 a0 = {0,0,0,0}, a1 = {0,0,0,0}, a2 = {0,0,0,0}, a3 = {0,0,0,0};
        #pragma unroll 4
        for (int s = 0; s < S; ++s) {
            float4 t0 = __ldg(F4 + (long)ip0[s] * (DDIM/4) + c4);
            float4 t1 = __ldg(F4 + (long)ip1[s] * (DDIM/4) + c4);
            float4 t2 = __ldg(F4 + (long)ip2[s] * (DDIM/4) + c4);
            float4 t3 = __ldg(F4 + (long)ip3[s] * (DDIM/4) + c4);
            a0.x += t0.x; a0.y += t0.y; a0.z += t0.z; a0.w += t0.w;
            a1.x += t1.x; a1.y += t1.y; a1.z += t1.z; a1.w += t1.w;
            a2.x += t2.x; a2.y += t2.y; a2.z += t2.z; a2.w += t2.w;
            a3.x += t3.x; a3.y += t3.y; a3.z += t3.z; a3.w += t3.w;
        }
        const float m0 = v0 ? invS : 0.0f, m1 = v1 ? invS : 0.0f;
        const float m2 = v2 ? invS : 0.0f, m3 = v3 ? invS : 0.0f;
        uint4 u0 = { f2tf32(a0.x*m0), f2tf32(a0.y*m0), f2tf32(a0.z*m0), f2tf32(a0.w*m0) };
        uint4 u1 = { f2tf32(a1.x*m1), f2tf32(a1.y*m1), f2tf32(a1.z*m1), f2tf32(a1.w*m1) };
        uint4 u2 = { f2tf32(a2.x*m2), f2tf32(a2.y*m2), f2tf32(a2.z*m2), f2tf32(a2.w*m2) };
        uint4 u3 = { f2tf32(a3.x*m3), f2tf32(a3.y*m3), f2tf32(a3.z*m3), f2tf32(a3.w*m3) };
        *reinterpret_cast<uint4*>(&As[(n0 + 0) * ASTRIDE + 4 * c4]) = u0;
        *reinterpret_cast<uint4*>(&As[(n0 + 1) * ASTRIDE + 4 * c4]) = u1;
        *reinterpret_cast<uint4*>(&As[(n0 + 2) * ASTRIDE + 4 * c4]) = u2;
        *reinterpret_cast<uint4*>(&As[(n0 + 3) * ASTRIDE + 4 * c4]) = u3;
    }
    __syncthreads();

    const int lane = tid & 31, warp = tid >> 5;
    const int g    = lane >> 2, t = lane & 3;
    const int mrow  = (warp & 1) * 16;
    const int nbase = (warp >> 1) * 32;
    const int kk = tid >> 6;
    const int n4 = (tid & 63) * 4;

    float d[4][4];
    #pragma unroll
    for (int j = 0; j < 4; ++j)
        #pragma unroll
        for (int c = 0; c < 4; ++c) d[j][c] = 0.0f;

    const uint32_t* a_lo = reinterpret_cast<const uint32_t*>(As) + (mrow + g) * ASTRIDE;
    const uint32_t* a_hi = a_lo + 8 * ASTRIDE;

    {
        float4 w = *reinterpret_cast<const float4*>(&W[kk * DDIM + n4]);
        uint4 u = { f2tf32(w.x), f2tf32(w.y), f2tf32(w.z), f2tf32(w.w) };
        *reinterpret_cast<uint4*>(&Ws[kk * WSTRIDE + n4]) = u;
    }
    __syncthreads();

    for (int kc = 0; kc < DDIM / 8; ++kc) {
        const uint32_t* Wb = Ws + (kc & 1) * (8 * WSTRIDE);
        if (kc + 1 < DDIM / 8) {
            float4 w = *reinterpret_cast<const float4*>(
                           &W[((kc + 1) * 8 + kk) * DDIM + n4]);
            uint4 u = { f2tf32(w.x), f2tf32(w.y), f2tf32(w.z), f2tf32(w.w) };
            *reinterpret_cast<uint4*>(
                &Ws[((kc + 1) & 1) * (8 * WSTRIDE) + kk * WSTRIDE + n4]) = u;
        }
        const int k0 = kc * 8;
        uint32_t fa0 = a_lo[k0 + t];
        uint32_t fa1 = a_hi[k0 + t];
        uint32_t fa2 = a_lo[k0 + t + 4];
        uint32_t fa3 = a_hi[k0 + t + 4];
        #pragma unroll
        for (int j = 0; j < 4; ++j) {
            int n = nbase + 8 * j + g;
            uint32_t b0 = Wb[t * WSTRIDE + n];
            uint32_t b1 = Wb[(t + 4) * WSTRIDE + n];
            mma_tf32(d[j], fa0, fa1, fa2, fa3, b0, b1);
        }
        __syncthreads();
    }

    #pragma unroll
    for (int j = 0; j < 4; ++j) {
        int col = nbase + 8 * j + 2 * t;
        float2 bbf = __ldg(reinterpret_cast<const float2*>(b + col));
        float2 lo, hi;
        lo.x = fmaxf(d[j][0] + bbf.x, 0.0f);
        lo.y = fmaxf(d[j][1] + bbf.y, 0.0f);
        hi.x = fmaxf(d[j][2] + bbf.x, 0.0f);
        hi.y = fmaxf(d[j][3] + bbf.y, 0.0f);
        *reinterpret_cast<float2*>(&As[(mrow + g)     * ASTRIDE + col]) = lo;
        *reinterpret_cast<float2*>(&As[(mrow + g + 8) * ASTRIDE + col]) = hi;
    }
    __syncthreads();

    #pragma unroll
    for (int rr = 0; rr < 2; ++rr) {
        int row = warp * 2 + rr;
        float s = 0.0f;
        #pragma unroll
        for (int jj = 0; jj < 8; ++jj) {
            float v = As[row * ASTRIDE + lane + 32 * jj];
            s = fmaf(v, v, s);
        }
        #pragma unroll
        for (int o = 16; o > 0; o >>= 1)
            s += __shfl_xor_sync(0xffffffffu, s, o);
        if (lane == 0)
            invN[row] = 1.0f / fmaxf(sqrtf(s), 1e-12f);
    }
    __syncthreads();

    float4* out4 = reinterpret_cast<float4*>(out);
    for (int i = tid; i < BM * (DDIM / 4); i += THREADS) {
        int r = i >> 6, c = i & 63;
        if (r < rows) {
            float4 v = *reinterpret_cast<const float4*>(&As[r * ASTRIDE + 4 * c]);
            float sc = invN[r];
            v.x *= sc; v.y *= sc; v.z *= sc; v.w *= sc;
            stg_stream(out4 + (long)(blockBase + r) * (DDIM / 4) + c, v);
        }
    }
}

extern "C" void kernel_launch(void* const* d_in, const int* in_sizes, int n_in,
                              void* d_out, int out_size)
{
    const int*   node_idx  = (const int*)  d_in[0];
    const int*   neigh_idx = (const int*)  d_in[1];
    const float* features  = (const float*)d_in[2];
    const float* W         = (const float*)d_in[3];
    const float* b         = (const float*)d_in[4];
    float*       out       = (float*)      d_out;

    const int n_nodes = in_sizes[0];
    const int n_samp  = in_sizes[1] / n_nodes;   // 32
    const int n_table = in_sizes[2] / DDIM;
    const int ntiles  = (n_nodes + BM - 1) / BM;

    const bool shapes_ok = (in_sizes[3] == DDIM * DDIM) && (in_sizes[4] == DDIM);

    if (shapes_ok && n_table <= NTAB_CAP && n_nodes <= NODE_CAP &&
        n_samp + 1 <= MAX_S) {
        const int n_vec = n_table * 32;
        cvt_f16_kernel<<<3125, 512>>>(
            reinterpret_cast<const float4*>(features), n_vec);
        cvt_w16_kernel<<<DDIM, DDIM>>>(W);

        const int ggrid = (n_nodes + GW - 1) / GW;
        gather_kernel<<<ggrid, THREADS>>>(node_idx, neigh_idx, n_nodes, n_samp);

        cudaFuncSetAttribute(gemm_kernel,
                             cudaFuncAttributeMaxDynamicSharedMemorySize, PG_SMEM);
        const int npairs = (ntiles + 1) / 2;
        const int mgrid  = (npairs < 148) ? npairs : 148;
        gemm_kernel<<<mgrid, GT, PG_SMEM>>>(b, out, n_nodes, ntiles);
    } else {
        cudaFuncSetAttribute(gsage_fused_f32,
                             cudaFuncAttributeMaxDynamicSharedMemorySize, SMEM_BYTES);
        const int grid = (n_nodes + BM - 1) / BM;
        gsage_fused_f32<<<grid, THREADS, SMEM_BYTES>>>(
            node_idx, neigh_idx, features, W, b, out, n_nodes, n_samp);
    }
}